// round 1
// baseline (speedup 1.0000x reference)
#include <cuda_runtime.h>
#include <cuda_bf16.h>
#include <math.h>

// Problem constants
#define BATCH 64
#define TT    512
#define DD    32
#define UU    512
#define SIGD  1056            // D + D*D
#define NG    1536            // 3*U
#define NCTA  128             // scan grid size (co-resident, 1 wave)

// ---------------- device scratch (static: no cudaMalloc allowed) ----------
__device__ float g_norm_sigs[(size_t)BATCH * TT * SIGD];   // 138 MB
__device__ float g_xproj   [(size_t)BATCH * TT * NG];      // 201 MB  (bias fused)
__device__ float g_fall    [(size_t)BATCH * TT * UU];      // 67 MB   (sigmoid fused)
__device__ float g_h[2][UU][BATCH];                        // h double buffer, [u][b]
__device__ unsigned int g_bar;                             // grid barrier counter

__device__ __forceinline__ float sigmoidf_(float v) {
    return 1.0f / (1.0f + expf(-v));
}

// ===========================================================================
// Kernel 1: signature stream -> g_norm_sigs  (64 CTAs, 1024 threads)
// thread (i=warp, j=lane) owns S2[i][j]; S1 kept per-lane, shared via shfl.
// ===========================================================================
__global__ void sig_kernel(const float* __restrict__ x) {
    const int b = blockIdx.x;
    extern __shared__ float s_x[];           // 512*32 floats = 64KB
    for (int e = threadIdx.x; e < TT * DD; e += blockDim.x)
        s_x[e] = x[(size_t)b * TT * DD + e];

    float* outb = g_norm_sigs + (size_t)b * TT * SIGD;
    for (int s = threadIdx.x; s < SIGD; s += blockDim.x)
        outb[s] = 0.0f;                       // t = 0 row is zeros
    __syncthreads();

    const int i = threadIdx.x >> 5;           // warp id = level-1 index i
    const int j = threadIdx.x & 31;           // lane    = index j
    float S2 = 0.0f;
    float S1j = 0.0f;                          // running S1 for index j (per lane)

    for (int t = 1; t < TT; ++t) {
        float dxj = s_x[t * DD + j] - s_x[(t - 1) * DD + j];
        float dxi = s_x[t * DD + i] - s_x[(t - 1) * DD + i];
        // S1 (before this increment) for index i = lane i's S1j
        float S1i_prev = __shfl_sync(0xffffffffu, S1j, i);
        S2 += S1i_prev * dxj + 0.5f * dxi * dxj;
        S1j += dxj;
        float invt = 1.0f / (float)t;
        float* outr = outb + (size_t)t * SIGD;
        outr[DD + i * DD + j] = S2 * invt;
        if (i == 0) outr[j] = S1j * invt;
    }
}

// ===========================================================================
// Kernel 2/3: fp32 SGEMM  C = act(A[M,K] @ B[K,N] + bias)
// BM=BN=128, BK=16, 256 threads, 8x8 register tile.
// MODE 0: forget gate  -> sigmoid(acc + bias[512+n])
// MODE 1: x projection -> acc + (n<512 ? bias[n] : bias[n+512])
// ===========================================================================
template <int KDIM, int NDIM, int MODE>
__global__ __launch_bounds__(256) void sgemm_kernel(
    const float* __restrict__ A, const float* __restrict__ B,
    const float* __restrict__ bias, float* __restrict__ C) {
    __shared__ float As[16][132];
    __shared__ float Bs[16][132];
    const int tid = threadIdx.x;
    const int m0 = blockIdx.y * 128;
    const int n0 = blockIdx.x * 128;
    const int tx = tid & 15;   // n dim
    const int ty = tid >> 4;   // m dim

    float acc[8][8];
#pragma unroll
    for (int ii = 0; ii < 8; ++ii)
#pragma unroll
        for (int jj = 0; jj < 8; ++jj) acc[ii][jj] = 0.0f;

    for (int k0 = 0; k0 < KDIM; k0 += 16) {
#pragma unroll
        for (int r = 0; r < 2; ++r) {   // A tile: 128 rows x 16 k
            int f = tid + r * 256;
            int row = f >> 2;
            int kc = (f & 3) * 4;
            float4 v = *(const float4*)&A[(size_t)(m0 + row) * KDIM + k0 + kc];
            As[kc + 0][row] = v.x;
            As[kc + 1][row] = v.y;
            As[kc + 2][row] = v.z;
            As[kc + 3][row] = v.w;
        }
#pragma unroll
        for (int r = 0; r < 2; ++r) {   // B tile: 16 k x 128 n
            int f = tid + r * 256;
            int kk = f >> 5;
            int nc = (f & 31) * 4;
            *(float4*)&Bs[kk][nc] =
                *(const float4*)&B[(size_t)(k0 + kk) * NDIM + n0 + nc];
        }
        __syncthreads();
#pragma unroll
        for (int kk = 0; kk < 16; ++kk) {
            float4 a0 = *(const float4*)&As[kk][ty * 8];
            float4 a1 = *(const float4*)&As[kk][ty * 8 + 4];
            float4 b0 = *(const float4*)&Bs[kk][tx * 8];
            float4 b1 = *(const float4*)&Bs[kk][tx * 8 + 4];
            float a[8] = {a0.x, a0.y, a0.z, a0.w, a1.x, a1.y, a1.z, a1.w};
            float bb[8] = {b0.x, b0.y, b0.z, b0.w, b1.x, b1.y, b1.z, b1.w};
#pragma unroll
            for (int ii = 0; ii < 8; ++ii)
#pragma unroll
                for (int jj = 0; jj < 8; ++jj) acc[ii][jj] += a[ii] * bb[jj];
        }
        __syncthreads();
    }

    // epilogue (vectorized stores)
#pragma unroll
    for (int ii = 0; ii < 8; ++ii) {
        int m = m0 + ty * 8 + ii;
#pragma unroll
        for (int half = 0; half < 2; ++half) {
            float4 v;
            float tmp[4];
#pragma unroll
            for (int q = 0; q < 4; ++q) {
                int jj = half * 4 + q;
                int n = n0 + tx * 8 + jj;
                float val = acc[ii][jj];
                if (MODE == 0) {
                    val = sigmoidf_(val + bias[512 + n]);
                } else {
                    val += (n < 512) ? bias[n] : bias[n + 512];
                }
                tmp[q] = val;
            }
            v.x = tmp[0]; v.y = tmp[1]; v.z = tmp[2]; v.w = tmp[3];
            *(float4*)&C[(size_t)m * NDIM + n0 + tx * 8 + half * 4] = v;
        }
    }
}

// ===========================================================================
// Kernel 4: persistent LSTM scan. 128 CTAs x 256 threads, 1 CTA/SM.
// CTA (bg, ns): batch half bg*32..+31, units u0 = ns*8 .. +7 (3 gate cols each).
// Weights resident in smem; h exchanged via L2 (ld.cg) + atomic grid barrier.
// ===========================================================================
__device__ __forceinline__ void grid_barrier(unsigned target) {
    __threadfence();
    __syncthreads();
    if (threadIdx.x == 0) {
        atomicAdd(&g_bar, 1u);
        while (*((volatile unsigned*)&g_bar) < target) { }
        __threadfence();
    }
    __syncthreads();
}

__global__ void reset_bar_kernel() { g_bar = 0u; }

__global__ __launch_bounds__(256, 1) void scan_kernel(
    const float* __restrict__ rk, float* __restrict__ out) {
    extern __shared__ float sm[];
    float* Wr_s = sm;                      // [24][520]
    float* h_s  = sm + 24 * 520;           // [512][32]  h_s[k][b_local]
    float* red  = h_s + 512 * 32;          // [128][25]  k-split partials

    const int tid = threadIdx.x;
    const int cta = blockIdx.x;
    const int bg = cta >> 6;               // batch group 0/1
    const int ns = cta & 63;               // unit slice
    const int u0 = ns * 8;
    const int B0 = bg * 32;

    // load resident weight slice: Wr_s[j][k] = rk[k*1536 + gcol(j)]
    for (int idx = tid; idx < 24 * 512; idx += 256) {
        int k = idx / 24;
        int j = idx - k * 24;
        int gc = (j >> 3) * 512 + u0 + (j & 7);
        Wr_s[j * 520 + k] = rk[(size_t)k * NG + gc];
    }
    // zero h buffer 0 (each CTA owns a disjoint (u-slice, b-half) patch)
    {
        int bl = tid >> 3, uu = tid & 7;
        g_h[0][u0 + uu][B0 + bl] = 0.0f;
    }
    grid_barrier(NCTA * 1u);

    const int kg = tid >> 6;               // k-split group 0..3
    const int t64 = tid & 63;
    const int bq = t64 & 7;                // 4-batch tile
    const int nq = t64 >> 3;               // 3-col tile
    const int bl_c = tid >> 3;             // owned cell: batch local
    const int uu_c = tid & 7;              // owned cell: unit local
    const int bglob = B0 + bl_c;
    const size_t xrow_stride = (size_t)NG;
    const size_t frow_stride = (size_t)UU;

    float c_state = 0.0f;
    int p = 0;

    for (int t = 0; t < TT; ++t) {
        // prefetch per-cell time-parallel terms (hides latency under GEMV)
        const float* xp = g_xproj + ((size_t)bglob * TT + t) * xrow_stride + u0 + uu_c;
        float xpi = xp[0];
        float xpc = xp[512];
        float xpo = xp[1024];
        float fgate = g_fall[((size_t)bglob * TT + t) * frow_stride + u0 + uu_c];

        // load h (previous step, all 512 units, 32 batches) via L2 (coherent)
        const float* hsrc = &g_h[p][0][0];
        for (int e = tid; e < 512 * 8; e += 256) {
            int k = e >> 3;
            int b4 = (e & 7) * 4;
            float4 v = __ldcg((const float4*)&hsrc[k * 64 + B0 + b4]);
            *(float4*)&h_s[k * 32 + b4] = v;
        }
        __syncthreads();

        // gates: acc[4 batches][3 cols] over k in [kg*128, kg*128+128)
        float acc[4][3];
#pragma unroll
        for (int a = 0; a < 4; ++a)
#pragma unroll
            for (int c2 = 0; c2 < 3; ++c2) acc[a][c2] = 0.0f;

        const float* w0 = &Wr_s[(nq * 3 + 0) * 520];
        const float* w1 = &Wr_s[(nq * 3 + 1) * 520];
        const float* w2 = &Wr_s[(nq * 3 + 2) * 520];
        const int kbase = kg * 128;
#pragma unroll 4
        for (int k4 = 0; k4 < 128; k4 += 4) {
            int k = kbase + k4;
            float4 wa = *(const float4*)&w0[k];
            float4 wb = *(const float4*)&w1[k];
            float4 wc = *(const float4*)&w2[k];
#pragma unroll
            for (int kk = 0; kk < 4; ++kk) {
                float4 hv = *(const float4*)&h_s[(k + kk) * 32 + bq * 4];
                float wav = (&wa.x)[kk];
                float wbv = (&wb.x)[kk];
                float wcv = (&wc.x)[kk];
                acc[0][0] += hv.x * wav; acc[0][1] += hv.x * wbv; acc[0][2] += hv.x * wcv;
                acc[1][0] += hv.y * wav; acc[1][1] += hv.y * wbv; acc[1][2] += hv.y * wcv;
                acc[2][0] += hv.z * wav; acc[2][1] += hv.z * wbv; acc[2][2] += hv.z * wcv;
                acc[3][0] += hv.w * wav; acc[3][1] += hv.w * wbv; acc[3][2] += hv.w * wcv;
            }
        }
        // k-split partials -> smem
#pragma unroll
        for (int a = 0; a < 4; ++a)
#pragma unroll
            for (int c2 = 0; c2 < 3; ++c2)
                red[(kg * 32 + bq * 4 + a) * 25 + nq * 3 + c2] = acc[a][c2];
        __syncthreads();

        // cell update: one (b, u) per thread
        float gi = 0.0f, gc = 0.0f, go = 0.0f;
#pragma unroll
        for (int kg2 = 0; kg2 < 4; ++kg2) {
            const float* r = &red[(kg2 * 32 + bl_c) * 25];
            gi += r[uu_c];
            gc += r[8 + uu_c];
            go += r[16 + uu_c];
        }
        float i_g = sigmoidf_(gi + xpi);
        float chat = tanhf(gc + xpc);
        float o_g = sigmoidf_(go + xpo);
        c_state = fgate * c_state + i_g * chat;
        float h = o_g * tanhf(c_state);

        if (t == TT - 1) {
            out[(size_t)bglob * UU + u0 + uu_c] = h;
        } else {
            g_h[1 - p][u0 + uu_c][B0 + bl_c] = h;
        }
        p ^= 1;
        grid_barrier(NCTA * (unsigned)(t + 2));
    }
}

// ===========================================================================
// launcher
// ===========================================================================
extern "C" void kernel_launch(void* const* d_in, const int* in_sizes, int n_in,
                              void* d_out, int out_size) {
    const float* x    = (const float*)d_in[0];   // (64,512,32)
    const float* ik   = (const float*)d_in[1];   // (32,1536)
    const float* rk   = (const float*)d_in[2];   // (512,1536)
    const float* fk   = (const float*)d_in[3];   // (1056,512)
    const float* bias = (const float*)d_in[4];   // (2048,)
    float* out = (float*)d_out;

    cudaFuncSetAttribute(sig_kernel,
                         cudaFuncAttributeMaxDynamicSharedMemorySize, 64 * 1024);
    cudaFuncSetAttribute(scan_kernel,
                         cudaFuncAttributeMaxDynamicSharedMemorySize, 129 * 1024);

    float* norm_sigs;  cudaGetSymbolAddress((void**)&norm_sigs, g_norm_sigs);
    float* xproj;      cudaGetSymbolAddress((void**)&xproj, g_xproj);
    float* fall;       cudaGetSymbolAddress((void**)&fall, g_fall);

    // 1. signature stream
    sig_kernel<<<BATCH, 1024, TT * DD * sizeof(float)>>>(x);

    // 2. forget gate GEMM + sigmoid  (M=32768, K=1056, N=512)
    {
        dim3 grid(UU / 128, (BATCH * TT) / 128);
        sgemm_kernel<SIGD, UU, 0><<<grid, 256>>>(norm_sigs, fk, bias, fall);
    }
    // 3. input projection GEMM + gate biases  (M=32768, K=32, N=1536)
    {
        dim3 grid(NG / 128, (BATCH * TT) / 128);
        sgemm_kernel<DD, NG, 1><<<grid, 256>>>(x, ik, bias, xproj);
    }
    // 4. persistent LSTM scan
    reset_bar_kernel<<<1, 1>>>();
    size_t smem = (size_t)(24 * 520 + 512 * 32 + 128 * 25) * sizeof(float);
    scan_kernel<<<NCTA, 256, smem>>>(rk, out);
}

// round 3
// speedup vs baseline: 1.0329x; 1.0329x over previous
#include <cuda_runtime.h>
#include <cuda_bf16.h>
#include <mma.h>
#include <math.h>
#include <stdint.h>

using namespace nvcuda;

// Problem constants
#define BATCH 64
#define TT    512
#define DD    32
#define UU    512
#define SIGD  1056            // D + D*D
#define NG    1536            // 3*U
#define NCTA  128             // scan grid size (co-resident, 1 wave)
#define MM    (BATCH * TT)    // 32768
#define KPAD  1088            // 34 * 32

// ---------------- device scratch (static: no cudaMalloc allowed) ----------
__device__ float g_norm_sigs[(size_t)MM * SIGD];           // 138 MB
__device__ float g_xproj   [(size_t)MM * NG];              // 201 MB  (bias fused)
__device__ float g_fall    [(size_t)MM * UU];              // 67 MB   (sigmoid fused)
__device__ float g_h[2][UU][BATCH];                        // h double buffer
__device__ unsigned int g_bar;                             // grid barrier counter

// bf16 hi/lo split operands for the forget GEMM (row-major, K padded)
__device__ __nv_bfloat16 g_Ah[(size_t)MM * KPAD];          // 71 MB
__device__ __nv_bfloat16 g_Al[(size_t)MM * KPAD];          // 71 MB
__device__ __nv_bfloat16 g_Bh[(size_t)KPAD * UU];          // 1.1 MB
__device__ __nv_bfloat16 g_Bl[(size_t)KPAD * UU];

__device__ __forceinline__ float sigmoidf_(float v) {
    return 1.0f / (1.0f + expf(-v));
}

// ===========================================================================
// Kernel 1: signature stream -> g_norm_sigs  (64 CTAs, 1024 threads)
// ===========================================================================
__global__ void sig_kernel(const float* __restrict__ x) {
    const int b = blockIdx.x;
    extern __shared__ float s_x[];           // 512*32 floats = 64KB
    for (int e = threadIdx.x; e < TT * DD; e += blockDim.x)
        s_x[e] = x[(size_t)b * TT * DD + e];

    float* outb = g_norm_sigs + (size_t)b * TT * SIGD;
    for (int s = threadIdx.x; s < SIGD; s += blockDim.x)
        outb[s] = 0.0f;
    __syncthreads();

    const int i = threadIdx.x >> 5;
    const int j = threadIdx.x & 31;
    float S2 = 0.0f;
    float S1j = 0.0f;

    for (int t = 1; t < TT; ++t) {
        float dxj = s_x[t * DD + j] - s_x[(t - 1) * DD + j];
        float dxi = s_x[t * DD + i] - s_x[(t - 1) * DD + i];
        float S1i_prev = __shfl_sync(0xffffffffu, S1j, i);
        S2 += S1i_prev * dxj + 0.5f * dxi * dxj;
        S1j += dxj;
        float invt = 1.0f / (float)t;
        float* outr = outb + (size_t)t * SIGD;
        outr[DD + i * DD + j] = S2 * invt;
        if (i == 0) outr[j] = S1j * invt;
    }
}

// ===========================================================================
// Kernel 1b: split A (norm_sigs) into hi/lo bf16 row-major [MM][KPAD]
// grid 4096 CTAs x 256 thr, each CTA does 8 rows.
// ===========================================================================
__global__ void split_A_kernel() {
    const int r0 = blockIdx.x * 8;
    for (int e = threadIdx.x; e < 8 * KPAD; e += 256) {
        int r = e / KPAD;
        int k = e - r * KPAD;
        int m = r0 + r;
        float v = (k < SIGD) ? g_norm_sigs[(size_t)m * SIGD + k] : 0.0f;
        __nv_bfloat16 hi = __float2bfloat16(v);
        float lo = v - __bfloat162float(hi);
        size_t o = (size_t)m * KPAD + k;
        g_Ah[o] = hi;
        g_Al[o] = __float2bfloat16(lo);
    }
}

// Kernel 1c: split B (forget kernel [1056][512]) into hi/lo bf16 [KPAD][512]
__global__ void split_B_kernel(const float* __restrict__ fk) {
    const size_t total = (size_t)KPAD * UU;
    for (size_t idx = blockIdx.x * 256 + threadIdx.x; idx < total;
         idx += (size_t)gridDim.x * 256) {
        int k = (int)(idx / UU);
        float v = (k < SIGD) ? fk[idx] : 0.0f;   // same linear layout for k<1056
        __nv_bfloat16 hi = __float2bfloat16(v);
        float lo = v - __bfloat162float(hi);
        g_Bh[idx] = hi;
        g_Bl[idx] = __float2bfloat16(lo);
    }
}

// ===========================================================================
// Kernel 2: WMMA bf16 3-split GEMM: g_fall = sigmoid(A@B + bias_f)
// CTA tile 128x128, 8 warps (4 x 2), warp tile 32x64, BK=32, 34 k-iters.
// ===========================================================================
__global__ __launch_bounds__(256) void fgemm_wmma_kernel(
    const float* __restrict__ bias, float* __restrict__ C) {
    __shared__ __nv_bfloat16 sAh[128][40];
    __shared__ __nv_bfloat16 sAl[128][40];
    __shared__ __nv_bfloat16 sBh[32][136];
    __shared__ __nv_bfloat16 sBl[32][136];
    __shared__ float sEpi[8][16][16];

    const int tid = threadIdx.x;
    const int warp = tid >> 5;
    const int lane = tid & 31;
    const int nt = blockIdx.x;           // 0..3
    const int mt = blockIdx.y;           // 0..255
    const int m0 = mt * 128;
    const int n0 = nt * 128;
    const int wm = warp & 3;             // warp row (32 rows each)
    const int wn = warp >> 2;            // warp col (64 cols each)

    wmma::fragment<wmma::accumulator, 16, 16, 16, float> acc[2][4];
#pragma unroll
    for (int im = 0; im < 2; ++im)
#pragma unroll
        for (int jn = 0; jn < 4; ++jn) wmma::fill_fragment(acc[im][jn], 0.0f);

    for (int k0 = 0; k0 < KPAD; k0 += 32) {
        // load A tiles (128x32 hi/lo) — 2 x uint4 per thread per matrix
#pragma unroll
        for (int r = 0; r < 2; ++r) {
            int f = tid + r * 256;
            int row = f >> 2;
            int kc = (f & 3) * 8;
            size_t src = (size_t)(m0 + row) * KPAD + k0 + kc;
            *(uint4*)&sAh[row][kc] = *(const uint4*)&g_Ah[src];
            *(uint4*)&sAl[row][kc] = *(const uint4*)&g_Al[src];
        }
        // load B tiles (32x128 hi/lo)
#pragma unroll
        for (int r = 0; r < 2; ++r) {
            int f = tid + r * 256;
            int kk = f >> 4;
            int nc = (f & 15) * 8;
            size_t src = (size_t)(k0 + kk) * UU + n0 + nc;
            *(uint4*)&sBh[kk][nc] = *(const uint4*)&g_Bh[src];
            *(uint4*)&sBl[kk][nc] = *(const uint4*)&g_Bl[src];
        }
        __syncthreads();

#pragma unroll
        for (int kk = 0; kk < 32; kk += 16) {
            wmma::fragment<wmma::matrix_b, 16, 16, 16, __nv_bfloat16,
                           wmma::row_major> bh[4], bl[4];
#pragma unroll
            for (int jn = 0; jn < 4; ++jn) {
                wmma::load_matrix_sync(bh[jn], &sBh[kk][wn * 64 + jn * 16], 136);
                wmma::load_matrix_sync(bl[jn], &sBl[kk][wn * 64 + jn * 16], 136);
            }
#pragma unroll
            for (int im = 0; im < 2; ++im) {
                wmma::fragment<wmma::matrix_a, 16, 16, 16, __nv_bfloat16,
                               wmma::row_major> ah, al;
                wmma::load_matrix_sync(ah, &sAh[wm * 32 + im * 16][kk], 40);
                wmma::load_matrix_sync(al, &sAl[wm * 32 + im * 16][kk], 40);
#pragma unroll
                for (int jn = 0; jn < 4; ++jn) {
                    wmma::mma_sync(acc[im][jn], ah, bh[jn], acc[im][jn]);
                    wmma::mma_sync(acc[im][jn], ah, bl[jn], acc[im][jn]);
                    wmma::mma_sync(acc[im][jn], al, bh[jn], acc[im][jn]);
                }
            }
        }
        __syncthreads();
    }

    // epilogue: per 16x16 tile -> smem scratch -> sigmoid(+bias) -> gmem
#pragma unroll
    for (int im = 0; im < 2; ++im) {
#pragma unroll
        for (int jn = 0; jn < 4; ++jn) {
            wmma::store_matrix_sync(&sEpi[warp][0][0], acc[im][jn], 16,
                                    wmma::mem_row_major);
            __syncwarp();
            int row = lane >> 1;
            int c0 = (lane & 1) * 8;
            int gm = m0 + wm * 32 + im * 16 + row;
            int gn = n0 + wn * 64 + jn * 16 + c0;
            float tmp[8];
#pragma unroll
            for (int q = 0; q < 8; ++q) {
                float v = sEpi[warp][row][c0 + q] + bias[512 + gn + q];
                tmp[q] = 1.0f / (1.0f + __expf(-v));
            }
            *(float4*)&C[(size_t)gm * UU + gn] =
                make_float4(tmp[0], tmp[1], tmp[2], tmp[3]);
            *(float4*)&C[(size_t)gm * UU + gn + 4] =
                make_float4(tmp[4], tmp[5], tmp[6], tmp[7]);
            __syncwarp();
        }
    }
}

// ===========================================================================
// Kernel 3: fp32 SGEMM for x projection (K=32) C = A@B + gate biases
// ===========================================================================
template <int KDIM, int NDIM>
__global__ __launch_bounds__(256) void sgemm_xproj_kernel(
    const float* __restrict__ A, const float* __restrict__ B,
    const float* __restrict__ bias, float* __restrict__ C) {
    __shared__ float As[16][132];
    __shared__ float Bs[16][132];
    const int tid = threadIdx.x;
    const int m0 = blockIdx.y * 128;
    const int n0 = blockIdx.x * 128;
    const int tx = tid & 15;
    const int ty = tid >> 4;

    float acc[8][8];
#pragma unroll
    for (int ii = 0; ii < 8; ++ii)
#pragma unroll
        for (int jj = 0; jj < 8; ++jj) acc[ii][jj] = 0.0f;

    for (int k0 = 0; k0 < KDIM; k0 += 16) {
#pragma unroll
        for (int r = 0; r < 2; ++r) {
            int f = tid + r * 256;
            int row = f >> 2;
            int kc = (f & 3) * 4;
            float4 v = *(const float4*)&A[(size_t)(m0 + row) * KDIM + k0 + kc];
            As[kc + 0][row] = v.x;
            As[kc + 1][row] = v.y;
            As[kc + 2][row] = v.z;
            As[kc + 3][row] = v.w;
        }
#pragma unroll
        for (int r = 0; r < 2; ++r) {
            int f = tid + r * 256;
            int kk = f >> 5;
            int nc = (f & 31) * 4;
            *(float4*)&Bs[kk][nc] =
                *(const float4*)&B[(size_t)(k0 + kk) * NDIM + n0 + nc];
        }
        __syncthreads();
#pragma unroll
        for (int kk = 0; kk < 16; ++kk) {
            float4 a0 = *(const float4*)&As[kk][ty * 8];
            float4 a1 = *(const float4*)&As[kk][ty * 8 + 4];
            float4 b0 = *(const float4*)&Bs[kk][tx * 8];
            float4 b1 = *(const float4*)&Bs[kk][tx * 8 + 4];
            float a[8] = {a0.x, a0.y, a0.z, a0.w, a1.x, a1.y, a1.z, a1.w};
            float bb[8] = {b0.x, b0.y, b0.z, b0.w, b1.x, b1.y, b1.z, b1.w};
#pragma unroll
            for (int ii = 0; ii < 8; ++ii)
#pragma unroll
                for (int jj = 0; jj < 8; ++jj) acc[ii][jj] += a[ii] * bb[jj];
        }
        __syncthreads();
    }

#pragma unroll
    for (int ii = 0; ii < 8; ++ii) {
        int m = m0 + ty * 8 + ii;
#pragma unroll
        for (int half = 0; half < 2; ++half) {
            float4 v;
            float tmp[4];
#pragma unroll
            for (int q = 0; q < 4; ++q) {
                int jj = half * 4 + q;
                int n = n0 + tx * 8 + jj;
                float val = acc[ii][jj];
                val += (n < 512) ? bias[n] : bias[n + 512];
                tmp[q] = val;
            }
            v.x = tmp[0]; v.y = tmp[1]; v.z = tmp[2]; v.w = tmp[3];
            *(float4*)&C[(size_t)m * NDIM + n0 + tx * 8 + half * 4] = v;
        }
    }
}

// ===========================================================================
// Kernel 4: persistent LSTM scan (unchanged from R1 passing version)
// ===========================================================================
__device__ __forceinline__ void grid_barrier(unsigned target) {
    __threadfence();
    __syncthreads();
    if (threadIdx.x == 0) {
        atomicAdd(&g_bar, 1u);
        while (*((volatile unsigned*)&g_bar) < target) { }
        __threadfence();
    }
    __syncthreads();
}

__global__ void reset_bar_kernel() { g_bar = 0u; }

__global__ __launch_bounds__(256, 1) void scan_kernel(
    const float* __restrict__ rk, float* __restrict__ out) {
    extern __shared__ float smf[];
    float* Wr_s = smf;                      // [24][520]
    float* h_s  = smf + 24 * 520;           // [512][32]
    float* red  = h_s + 512 * 32;           // [128][25]

    const int tid = threadIdx.x;
    const int cta = blockIdx.x;
    const int bg = cta >> 6;
    const int ns = cta & 63;
    const int u0 = ns * 8;
    const int B0 = bg * 32;

    for (int idx = tid; idx < 24 * 512; idx += 256) {
        int k = idx / 24;
        int j = idx - k * 24;
        int gc = (j >> 3) * 512 + u0 + (j & 7);
        Wr_s[j * 520 + k] = rk[(size_t)k * NG + gc];
    }
    {
        int bl = tid >> 3, uu = tid & 7;
        g_h[0][u0 + uu][B0 + bl] = 0.0f;
    }
    grid_barrier(NCTA * 1u);

    const int kg = tid >> 6;
    const int t64 = tid & 63;
    const int bq = t64 & 7;
    const int nq = t64 >> 3;
    const int bl_c = tid >> 3;
    const int uu_c = tid & 7;
    const int bglob = B0 + bl_c;

    float c_state = 0.0f;
    int p = 0;

    for (int t = 0; t < TT; ++t) {
        const float* xp = g_xproj + ((size_t)bglob * TT + t) * NG + u0 + uu_c;
        float xpi = xp[0];
        float xpc = xp[512];
        float xpo = xp[1024];
        float fgate = g_fall[((size_t)bglob * TT + t) * UU + u0 + uu_c];

        const float* hsrc = &g_h[p][0][0];
        for (int e = tid; e < 512 * 8; e += 256) {
            int k = e >> 3;
            int b4 = (e & 7) * 4;
            float4 v = __ldcg((const float4*)&hsrc[k * 64 + B0 + b4]);
            *(float4*)&h_s[k * 32 + b4] = v;
        }
        __syncthreads();

        float acc[4][3];
#pragma unroll
        for (int a = 0; a < 4; ++a)
#pragma unroll
            for (int c2 = 0; c2 < 3; ++c2) acc[a][c2] = 0.0f;

        const float* w0 = &Wr_s[(nq * 3 + 0) * 520];
        const float* w1 = &Wr_s[(nq * 3 + 1) * 520];
        const float* w2 = &Wr_s[(nq * 3 + 2) * 520];
        const int kbase = kg * 128;
#pragma unroll 4
        for (int k4 = 0; k4 < 128; k4 += 4) {
            int k = kbase + k4;
            float4 wa = *(const float4*)&w0[k];
            float4 wb = *(const float4*)&w1[k];
            float4 wc = *(const float4*)&w2[k];
#pragma unroll
            for (int kk = 0; kk < 4; ++kk) {
                float4 hv = *(const float4*)&h_s[(k + kk) * 32 + bq * 4];
                float wav = (&wa.x)[kk];
                float wbv = (&wb.x)[kk];
                float wcv = (&wc.x)[kk];
                acc[0][0] += hv.x * wav; acc[0][1] += hv.x * wbv; acc[0][2] += hv.x * wcv;
                acc[1][0] += hv.y * wav; acc[1][1] += hv.y * wbv; acc[1][2] += hv.y * wcv;
                acc[2][0] += hv.z * wav; acc[2][1] += hv.z * wbv; acc[2][2] += hv.z * wcv;
                acc[3][0] += hv.w * wav; acc[3][1] += hv.w * wbv; acc[3][2] += hv.w * wcv;
            }
        }
#pragma unroll
        for (int a = 0; a < 4; ++a)
#pragma unroll
            for (int c2 = 0; c2 < 3; ++c2)
                red[(kg * 32 + bq * 4 + a) * 25 + nq * 3 + c2] = acc[a][c2];
        __syncthreads();

        float gi = 0.0f, gc = 0.0f, go = 0.0f;
#pragma unroll
        for (int kg2 = 0; kg2 < 4; ++kg2) {
            const float* r = &red[(kg2 * 32 + bl_c) * 25];
            gi += r[uu_c];
            gc += r[8 + uu_c];
            go += r[16 + uu_c];
        }
        float i_g = sigmoidf_(gi + xpi);
        float chat = tanhf(gc + xpc);
        float o_g = sigmoidf_(go + xpo);
        c_state = fgate * c_state + i_g * chat;
        float h = o_g * tanhf(c_state);

        if (t == TT - 1) {
            out[(size_t)bglob * UU + u0 + uu_c] = h;
        } else {
            g_h[1 - p][u0 + uu_c][B0 + bl_c] = h;
        }
        p ^= 1;
        grid_barrier(NCTA * (unsigned)(t + 2));
    }
}

// ===========================================================================
// launcher
// ===========================================================================
extern "C" void kernel_launch(void* const* d_in, const int* in_sizes, int n_in,
                              void* d_out, int out_size) {
    const float* x    = (const float*)d_in[0];   // (64,512,32)
    const float* ik   = (const float*)d_in[1];   // (32,1536)
    const float* rk   = (const float*)d_in[2];   // (512,1536)
    const float* fk   = (const float*)d_in[3];   // (1056,512)
    const float* bias = (const float*)d_in[4];   // (2048,)
    float* out = (float*)d_out;

    cudaFuncSetAttribute(sig_kernel,
                         cudaFuncAttributeMaxDynamicSharedMemorySize, 64 * 1024);
    cudaFuncSetAttribute(scan_kernel,
                         cudaFuncAttributeMaxDynamicSharedMemorySize, 129 * 1024);

    float* xproj;  cudaGetSymbolAddress((void**)&xproj, g_xproj);
    float* fall;   cudaGetSymbolAddress((void**)&fall, g_fall);

    // 0. barrier reset
    reset_bar_kernel<<<1, 1>>>();

    // 1. signature stream
    sig_kernel<<<BATCH, 1024, TT * DD * sizeof(float)>>>(x);

    // 1b/1c. bf16 hi/lo split
    split_A_kernel<<<MM / 8, 256>>>();
    split_B_kernel<<<256, 256>>>(fk);

    // 2. forget gate GEMM + sigmoid via WMMA bf16 3-split
    fgemm_wmma_kernel<<<dim3(UU / 128, MM / 128), 256>>>(bias, fall);

    // 3. input projection GEMM + gate biases (fp32 SGEMM, K=32)
    {
        dim3 grid(NG / 128, MM / 128);
        sgemm_xproj_kernel<DD, NG><<<grid, 256>>>(x, ik, bias, xproj);
    }

    // 4. persistent LSTM scan
    size_t smem = (size_t)(24 * 520 + 512 * 32 + 128 * 25) * sizeof(float);
    scan_kernel<<<NCTA, 256, smem>>>(rk, out);
}

// round 4
// speedup vs baseline: 1.5726x; 1.5226x over previous
#include <cuda_runtime.h>
#include <cuda_bf16.h>
#include <mma.h>
#include <math.h>
#include <stdint.h>

using namespace nvcuda;

// Problem constants
#define BATCH 64
#define TT    512
#define DD    32
#define UU    512
#define SIGD  1056            // D + D*D
#define NG    1536            // 3*U
#define NCTA  128             // scan grid size (co-resident, 1 wave)
#define MM    (BATCH * TT)    // 32768
#define KPAD  1088            // 34 * 32

// ---------------- device scratch (static: no cudaMalloc allowed) ----------
__device__ float g_norm_sigs[(size_t)MM * SIGD];           // 138 MB
__device__ float g_xproj   [(size_t)MM * NG];              // 201 MB  (bias fused)
__device__ float g_fall    [(size_t)MM * UU];              // 67 MB   (sigmoid fused)
__device__ unsigned int g_hbf[2][BATCH][UU];               // h packed bf16 hi|lo<<16
__device__ unsigned int g_bar;                             // grid barrier counter

// bf16 hi/lo split operands for the forget GEMM (row-major, K padded)
__device__ __nv_bfloat16 g_Ah[(size_t)MM * KPAD];          // 71 MB
__device__ __nv_bfloat16 g_Al[(size_t)MM * KPAD];          // 71 MB
__device__ __nv_bfloat16 g_Bh[(size_t)KPAD * UU];          // 1.1 MB
__device__ __nv_bfloat16 g_Bl[(size_t)KPAD * UU];

__device__ __forceinline__ float sigmoidf_(float v) {
    return 1.0f / (1.0f + expf(-v));
}

// ===========================================================================
// Kernel 1: signature stream -> g_norm_sigs  (64 CTAs, 1024 threads)
// ===========================================================================
__global__ void sig_kernel(const float* __restrict__ x) {
    const int b = blockIdx.x;
    extern __shared__ float s_x[];           // 512*32 floats = 64KB
    for (int e = threadIdx.x; e < TT * DD; e += blockDim.x)
        s_x[e] = x[(size_t)b * TT * DD + e];

    float* outb = g_norm_sigs + (size_t)b * TT * SIGD;
    for (int s = threadIdx.x; s < SIGD; s += blockDim.x)
        outb[s] = 0.0f;
    __syncthreads();

    const int i = threadIdx.x >> 5;
    const int j = threadIdx.x & 31;
    float S2 = 0.0f;
    float S1j = 0.0f;

    for (int t = 1; t < TT; ++t) {
        float dxj = s_x[t * DD + j] - s_x[(t - 1) * DD + j];
        float dxi = s_x[t * DD + i] - s_x[(t - 1) * DD + i];
        float S1i_prev = __shfl_sync(0xffffffffu, S1j, i);
        S2 += S1i_prev * dxj + 0.5f * dxi * dxj;
        S1j += dxj;
        float invt = 1.0f / (float)t;
        float* outr = outb + (size_t)t * SIGD;
        outr[DD + i * DD + j] = S2 * invt;
        if (i == 0) outr[j] = S1j * invt;
    }
}

// ===========================================================================
// Kernel 1b: split A (norm_sigs) into hi/lo bf16 row-major [MM][KPAD]
// ===========================================================================
__global__ void split_A_kernel() {
    const int r0 = blockIdx.x * 8;
    for (int e = threadIdx.x; e < 8 * KPAD; e += 256) {
        int r = e / KPAD;
        int k = e - r * KPAD;
        int m = r0 + r;
        float v = (k < SIGD) ? g_norm_sigs[(size_t)m * SIGD + k] : 0.0f;
        __nv_bfloat16 hi = __float2bfloat16(v);
        float lo = v - __bfloat162float(hi);
        size_t o = (size_t)m * KPAD + k;
        g_Ah[o] = hi;
        g_Al[o] = __float2bfloat16(lo);
    }
}

// Kernel 1c: split B (forget kernel [1056][512]) into hi/lo bf16 [KPAD][512]
__global__ void split_B_kernel(const float* __restrict__ fk) {
    const size_t total = (size_t)KPAD * UU;
    for (size_t idx = blockIdx.x * 256 + threadIdx.x; idx < total;
         idx += (size_t)gridDim.x * 256) {
        int k = (int)(idx / UU);
        float v = (k < SIGD) ? fk[idx] : 0.0f;
        __nv_bfloat16 hi = __float2bfloat16(v);
        float lo = v - __bfloat162float(hi);
        g_Bh[idx] = hi;
        g_Bl[idx] = __float2bfloat16(lo);
    }
}

// ===========================================================================
// Kernel 2: WMMA bf16 3-split GEMM: g_fall = sigmoid(A@B + bias_f)
// ===========================================================================
__global__ __launch_bounds__(256) void fgemm_wmma_kernel(
    const float* __restrict__ bias, float* __restrict__ C) {
    __shared__ __nv_bfloat16 sAh[128][40];
    __shared__ __nv_bfloat16 sAl[128][40];
    __shared__ __nv_bfloat16 sBh[32][136];
    __shared__ __nv_bfloat16 sBl[32][136];
    __shared__ float sEpi[8][16][16];

    const int tid = threadIdx.x;
    const int warp = tid >> 5;
    const int lane = tid & 31;
    const int nt = blockIdx.x;
    const int mt = blockIdx.y;
    const int m0 = mt * 128;
    const int n0 = nt * 128;
    const int wm = warp & 3;
    const int wn = warp >> 2;

    wmma::fragment<wmma::accumulator, 16, 16, 16, float> acc[2][4];
#pragma unroll
    for (int im = 0; im < 2; ++im)
#pragma unroll
        for (int jn = 0; jn < 4; ++jn) wmma::fill_fragment(acc[im][jn], 0.0f);

    for (int k0 = 0; k0 < KPAD; k0 += 32) {
#pragma unroll
        for (int r = 0; r < 2; ++r) {
            int f = tid + r * 256;
            int row = f >> 2;
            int kc = (f & 3) * 8;
            size_t src = (size_t)(m0 + row) * KPAD + k0 + kc;
            *(uint4*)&sAh[row][kc] = *(const uint4*)&g_Ah[src];
            *(uint4*)&sAl[row][kc] = *(const uint4*)&g_Al[src];
        }
#pragma unroll
        for (int r = 0; r < 2; ++r) {
            int f = tid + r * 256;
            int kk = f >> 4;
            int nc = (f & 15) * 8;
            size_t src = (size_t)(k0 + kk) * UU + n0 + nc;
            *(uint4*)&sBh[kk][nc] = *(const uint4*)&g_Bh[src];
            *(uint4*)&sBl[kk][nc] = *(const uint4*)&g_Bl[src];
        }
        __syncthreads();

#pragma unroll
        for (int kk = 0; kk < 32; kk += 16) {
            wmma::fragment<wmma::matrix_b, 16, 16, 16, __nv_bfloat16,
                           wmma::row_major> bh[4], bl[4];
#pragma unroll
            for (int jn = 0; jn < 4; ++jn) {
                wmma::load_matrix_sync(bh[jn], &sBh[kk][wn * 64 + jn * 16], 136);
                wmma::load_matrix_sync(bl[jn], &sBl[kk][wn * 64 + jn * 16], 136);
            }
#pragma unroll
            for (int im = 0; im < 2; ++im) {
                wmma::fragment<wmma::matrix_a, 16, 16, 16, __nv_bfloat16,
                               wmma::row_major> ah, al;
                wmma::load_matrix_sync(ah, &sAh[wm * 32 + im * 16][kk], 40);
                wmma::load_matrix_sync(al, &sAl[wm * 32 + im * 16][kk], 40);
#pragma unroll
                for (int jn = 0; jn < 4; ++jn) {
                    wmma::mma_sync(acc[im][jn], ah, bh[jn], acc[im][jn]);
                    wmma::mma_sync(acc[im][jn], ah, bl[jn], acc[im][jn]);
                    wmma::mma_sync(acc[im][jn], al, bh[jn], acc[im][jn]);
                }
            }
        }
        __syncthreads();
    }

#pragma unroll
    for (int im = 0; im < 2; ++im) {
#pragma unroll
        for (int jn = 0; jn < 4; ++jn) {
            wmma::store_matrix_sync(&sEpi[warp][0][0], acc[im][jn], 16,
                                    wmma::mem_row_major);
            __syncwarp();
            int row = lane >> 1;
            int c0 = (lane & 1) * 8;
            int gm = m0 + wm * 32 + im * 16 + row;
            int gn = n0 + wn * 64 + jn * 16 + c0;
            float tmp[8];
#pragma unroll
            for (int q = 0; q < 8; ++q) {
                float v = sEpi[warp][row][c0 + q] + bias[512 + gn + q];
                tmp[q] = 1.0f / (1.0f + __expf(-v));
            }
            *(float4*)&C[(size_t)gm * UU + gn] =
                make_float4(tmp[0], tmp[1], tmp[2], tmp[3]);
            *(float4*)&C[(size_t)gm * UU + gn + 4] =
                make_float4(tmp[4], tmp[5], tmp[6], tmp[7]);
            __syncwarp();
        }
    }
}

// ===========================================================================
// Kernel 3: fp32 SGEMM for x projection (K=32) C = A@B + gate biases
// ===========================================================================
template <int KDIM, int NDIM>
__global__ __launch_bounds__(256) void sgemm_xproj_kernel(
    const float* __restrict__ A, const float* __restrict__ B,
    const float* __restrict__ bias, float* __restrict__ C) {
    __shared__ float As[16][132];
    __shared__ float Bs[16][132];
    const int tid = threadIdx.x;
    const int m0 = blockIdx.y * 128;
    const int n0 = blockIdx.x * 128;
    const int tx = tid & 15;
    const int ty = tid >> 4;

    float acc[8][8];
#pragma unroll
    for (int ii = 0; ii < 8; ++ii)
#pragma unroll
        for (int jj = 0; jj < 8; ++jj) acc[ii][jj] = 0.0f;

    for (int k0 = 0; k0 < KDIM; k0 += 16) {
#pragma unroll
        for (int r = 0; r < 2; ++r) {
            int f = tid + r * 256;
            int row = f >> 2;
            int kc = (f & 3) * 4;
            float4 v = *(const float4*)&A[(size_t)(m0 + row) * KDIM + k0 + kc];
            As[kc + 0][row] = v.x;
            As[kc + 1][row] = v.y;
            As[kc + 2][row] = v.z;
            As[kc + 3][row] = v.w;
        }
#pragma unroll
        for (int r = 0; r < 2; ++r) {
            int f = tid + r * 256;
            int kk = f >> 5;
            int nc = (f & 31) * 4;
            *(float4*)&Bs[kk][nc] =
                *(const float4*)&B[(size_t)(k0 + kk) * NDIM + n0 + nc];
        }
        __syncthreads();
#pragma unroll
        for (int kk = 0; kk < 16; ++kk) {
            float4 a0 = *(const float4*)&As[kk][ty * 8];
            float4 a1 = *(const float4*)&As[kk][ty * 8 + 4];
            float4 b0 = *(const float4*)&Bs[kk][tx * 8];
            float4 b1 = *(const float4*)&Bs[kk][tx * 8 + 4];
            float a[8] = {a0.x, a0.y, a0.z, a0.w, a1.x, a1.y, a1.z, a1.w};
            float bb[8] = {b0.x, b0.y, b0.z, b0.w, b1.x, b1.y, b1.z, b1.w};
#pragma unroll
            for (int ii = 0; ii < 8; ++ii)
#pragma unroll
                for (int jj = 0; jj < 8; ++jj) acc[ii][jj] += a[ii] * bb[jj];
        }
        __syncthreads();
    }

#pragma unroll
    for (int ii = 0; ii < 8; ++ii) {
        int m = m0 + ty * 8 + ii;
#pragma unroll
        for (int half = 0; half < 2; ++half) {
            float4 v;
            float tmp[4];
#pragma unroll
            for (int q = 0; q < 4; ++q) {
                int jj = half * 4 + q;
                int n = n0 + tx * 8 + jj;
                float val = acc[ii][jj];
                val += (n < 512) ? bias[n] : bias[n + 512];
                tmp[q] = val;
            }
            v.x = tmp[0]; v.y = tmp[1]; v.z = tmp[2]; v.w = tmp[3];
            *(float4*)&C[(size_t)m * NDIM + n0 + tx * 8 + half * 4] = v;
        }
    }
}

// ===========================================================================
// Kernel 4: persistent LSTM scan with WMMA bf16 hi/lo GEMV per step.
// 128 CTAs x 256 threads. CTA (mi, uj): batches mi*16..+15, units uj*16..+15;
// owns gate cols {U0..U0+15, 512+U0.., 1024+U0..} -> no cross-CTA gate traffic.
// h exchanged via gmem packed bf16 (hi | lo<<16) + grid barrier.
// ===========================================================================
__device__ __forceinline__ void grid_barrier(unsigned target) {
    __threadfence();
    __syncthreads();
    if (threadIdx.x == 0) {
        atomicAdd(&g_bar, 1u);
        while (*((volatile unsigned*)&g_bar) < target) { }
        __threadfence();
    }
    __syncthreads();
}

__global__ void reset_bar_kernel() { g_bar = 0u; }

// smem layout (in elements/bytes)
#define SWH_OFF  0                        // ushort [512][56]
#define SWL_OFF  (512 * 56)               // ushort [512][56]
#define SHH_OFF  (2 * 512 * 56)           // ushort [16][520]
#define SHL_OFF  (2 * 512 * 56 + 16 * 520)
#define SUS_TOT  (2 * 512 * 56 + 2 * 16 * 520)     // ushort count
#define SRED_BYTE_OFF ((SUS_TOT * 2 + 15) & ~15)
#define SCAN_SMEM (SRED_BYTE_OFF + 8 * 3 * 256 * 4)

__global__ __launch_bounds__(256, 1) void scan_kernel(
    const float* __restrict__ rk, float* __restrict__ out) {
    extern __shared__ char smraw[];
    unsigned short* sWh = (unsigned short*)smraw + SWH_OFF;
    unsigned short* sWl = (unsigned short*)smraw + SWL_OFF;
    unsigned short* sHh = (unsigned short*)smraw + SHH_OFF;
    unsigned short* sHl = (unsigned short*)smraw + SHL_OFF;
    float* sRed = (float*)(smraw + SRED_BYTE_OFF);   // [8][3][16][16]

    const int tid = threadIdx.x;
    const int warp = tid >> 5;
    const int mi = blockIdx.x >> 5;          // 0..3  batch tile
    const int uj = blockIdx.x & 31;          // 0..31 unit tile
    const int B0 = mi * 16;
    const int U0 = uj * 16;

    // load + split weight slice: sW[k][c], c = gate*16 + cc, col = gate*512+U0+cc
    for (int idx = tid; idx < 512 * 48; idx += 256) {
        int k = idx / 48;
        int c = idx - k * 48;
        int gcol = (c >> 4) * 512 + U0 + (c & 15);
        float v = rk[(size_t)k * NG + gcol];
        __nv_bfloat16 hi = __float2bfloat16(v);
        float lo = v - __bfloat162float(hi);
        sWh[k * 56 + c] = __bfloat16_as_ushort(hi);
        sWl[k * 56 + c] = __bfloat16_as_ushort(__float2bfloat16(lo));
    }
    // zero h buffer 0 for owned cells
    {
        int bl = tid >> 4, ul = tid & 15;
        g_hbf[0][B0 + bl][U0 + ul] = 0u;
    }
    grid_barrier(NCTA * 1u);

    const int bl_c = tid >> 4;               // owned cell batch local
    const int ul_c = tid & 15;               // owned cell unit local
    const int bglob = B0 + bl_c;
    const int uglob = U0 + ul_c;

    float c_state = 0.0f;
    int p = 0;

    for (int t = 0; t < TT; ++t) {
        // time-parallel terms for own cell
        const float* xp = g_xproj + ((size_t)bglob * TT + t) * NG + uglob;
        float xpi = xp[0];
        float xpc = xp[512];
        float xpo = xp[1024];
        float fgate = g_fall[((size_t)bglob * TT + t) * UU + uglob];

        // load h block [16][512] packed, unpack to smem hi/lo
        const unsigned int* hsrc = &g_hbf[p][B0][0];
#pragma unroll
        for (int i = 0; i < 32; ++i) {
            int e = tid + i * 256;
            int row = e >> 9;
            int col = e & 511;
            unsigned int v = __ldcg(&hsrc[row * UU + col]);
            sHh[row * 520 + col] = (unsigned short)(v & 0xffffu);
            sHl[row * 520 + col] = (unsigned short)(v >> 16);
        }
        __syncthreads();

        // warp `warp` handles k in [warp*64, warp*64+64), 3 n-tiles
        {
            wmma::fragment<wmma::accumulator, 16, 16, 16, float> acc[3];
#pragma unroll
            for (int n = 0; n < 3; ++n) wmma::fill_fragment(acc[n], 0.0f);
#pragma unroll
            for (int kt = 0; kt < 4; ++kt) {
                int k0 = warp * 64 + kt * 16;
                wmma::fragment<wmma::matrix_a, 16, 16, 16, __nv_bfloat16,
                               wmma::row_major> ah, al;
                wmma::load_matrix_sync(ah, (__nv_bfloat16*)&sHh[k0], 520);
                wmma::load_matrix_sync(al, (__nv_bfloat16*)&sHl[k0], 520);
#pragma unroll
                for (int n = 0; n < 3; ++n) {
                    wmma::fragment<wmma::matrix_b, 16, 16, 16, __nv_bfloat16,
                                   wmma::row_major> bh, blo;
                    wmma::load_matrix_sync(bh, (__nv_bfloat16*)&sWh[k0 * 56 + n * 16], 56);
                    wmma::load_matrix_sync(blo, (__nv_bfloat16*)&sWl[k0 * 56 + n * 16], 56);
                    wmma::mma_sync(acc[n], ah, bh, acc[n]);
                    wmma::mma_sync(acc[n], ah, blo, acc[n]);
                    wmma::mma_sync(acc[n], al, bh, acc[n]);
                }
            }
#pragma unroll
            for (int n = 0; n < 3; ++n)
                wmma::store_matrix_sync(&sRed[(warp * 3 + n) * 256], acc[n], 16,
                                        wmma::mem_row_major);
        }
        __syncthreads();

        // cell update: one (b,u) per thread; reduce 8 warp partials per gate
        float gi = 0.0f, gc = 0.0f, go = 0.0f;
        const int cell = bl_c * 16 + ul_c;
#pragma unroll
        for (int w = 0; w < 8; ++w) {
            gi += sRed[(w * 3 + 0) * 256 + cell];
            gc += sRed[(w * 3 + 1) * 256 + cell];
            go += sRed[(w * 3 + 2) * 256 + cell];
        }
        float i_g = sigmoidf_(gi + xpi);
        float chat = tanhf(gc + xpc);
        float o_g = sigmoidf_(go + xpo);
        c_state = fgate * c_state + i_g * chat;
        float h = o_g * tanhf(c_state);

        if (t == TT - 1) {
            out[(size_t)bglob * UU + uglob] = h;
        } else {
            __nv_bfloat16 hb = __float2bfloat16(h);
            float lo = h - __bfloat162float(hb);
            unsigned int pack = (unsigned int)__bfloat16_as_ushort(hb) |
                                ((unsigned int)__bfloat16_as_ushort(
                                     __float2bfloat16(lo)) << 16);
            g_hbf[1 - p][bglob][uglob] = pack;
        }
        p ^= 1;
        grid_barrier(NCTA * (unsigned)(t + 2));
    }
}

// ===========================================================================
// launcher
// ===========================================================================
extern "C" void kernel_launch(void* const* d_in, const int* in_sizes, int n_in,
                              void* d_out, int out_size) {
    const float* x    = (const float*)d_in[0];   // (64,512,32)
    const float* ik   = (const float*)d_in[1];   // (32,1536)
    const float* rk   = (const float*)d_in[2];   // (512,1536)
    const float* fk   = (const float*)d_in[3];   // (1056,512)
    const float* bias = (const float*)d_in[4];   // (2048,)
    float* out = (float*)d_out;

    cudaFuncSetAttribute(sig_kernel,
                         cudaFuncAttributeMaxDynamicSharedMemorySize, 64 * 1024);
    cudaFuncSetAttribute(scan_kernel,
                         cudaFuncAttributeMaxDynamicSharedMemorySize, SCAN_SMEM);

    float* xproj;  cudaGetSymbolAddress((void**)&xproj, g_xproj);
    float* fall;   cudaGetSymbolAddress((void**)&fall, g_fall);

    // 0. barrier reset
    reset_bar_kernel<<<1, 1>>>();

    // 1. signature stream
    sig_kernel<<<BATCH, 1024, TT * DD * sizeof(float)>>>(x);

    // 1b/1c. bf16 hi/lo split for the forget GEMM
    split_A_kernel<<<MM / 8, 256>>>();
    split_B_kernel<<<256, 256>>>(fk);

    // 2. forget gate GEMM + sigmoid via WMMA bf16 3-split
    fgemm_wmma_kernel<<<dim3(UU / 128, MM / 128), 256>>>(bias, fall);

    // 3. input projection GEMM + gate biases (fp32 SGEMM, K=32)
    {
        dim3 grid(NG / 128, MM / 128);
        sgemm_xproj_kernel<DD, NG><<<grid, 256>>>(x, ik, bias, xproj);
    }

    // 4. persistent LSTM scan (WMMA per-step GEMV)
    scan_kernel<<<NCTA, 256, SCAN_SMEM>>>(rk, out);
}

// round 5
// speedup vs baseline: 1.7287x; 1.0993x over previous
#include <cuda_runtime.h>
#include <cuda_bf16.h>
#include <mma.h>
#include <math.h>
#include <stdint.h>

using namespace nvcuda;

// Problem constants
#define BATCH 64
#define TT    512
#define DD    32
#define UU    512
#define SIGD  1056            // D + D*D
#define NG    1536            // 3*U
#define NCTA  128             // scan grid size
#define MM    (BATCH * TT)    // 32768
#define KPAD  1088            // 34 * 32

// ---------------- device scratch (static: no cudaMalloc allowed) ----------
__device__ float g_xproj[(size_t)MM * NG];                 // 201 MB  (bias fused)
__device__ float g_fall [(size_t)MM * UU];                 // 67 MB   (sigmoid fused)
__device__ unsigned short g_hh[2][BATCH][UU];              // h hi bf16 plane
__device__ unsigned short g_hl[2][BATCH][UU];              // h lo bf16 plane
__device__ unsigned int g_bars[4][32];                     // per-group barrier ctrs

// bf16 hi/lo split operands for the forget GEMM (row-major, K padded)
__device__ __nv_bfloat16 g_Ah[(size_t)MM * KPAD];          // 71 MB
__device__ __nv_bfloat16 g_Al[(size_t)MM * KPAD];          // 71 MB
__device__ __nv_bfloat16 g_Bh[(size_t)KPAD * UU];          // 1.1 MB
__device__ __nv_bfloat16 g_Bl[(size_t)KPAD * UU];

__device__ __forceinline__ float sigmoidf_(float v) {
    return 1.0f / (1.0f + __expf(-v));
}
__device__ __forceinline__ float tanhf_(float v) {
    return 2.0f / (1.0f + __expf(-2.0f * v)) - 1.0f;
}

// ===========================================================================
// Kernel 1: signature stream -> g_Ah/g_Al directly (hi/lo bf16, [MM][KPAD])
// 64 CTAs x 1024 threads. warp i = level-1 index i, lane j = index j.
// ===========================================================================
__global__ void sig_kernel(const float* __restrict__ x) {
    const int b = blockIdx.x;
    extern __shared__ float s_x[];           // 512*32 floats = 64KB
    for (int e = threadIdx.x; e < TT * DD; e += blockDim.x)
        s_x[e] = x[(size_t)b * TT * DD + e];

    const size_t rowbase = (size_t)b * TT * KPAD;
    // t = 0 row: all zeros
    for (int kk = threadIdx.x; kk < KPAD; kk += blockDim.x) {
        g_Ah[rowbase + kk] = __float2bfloat16(0.0f);
        g_Al[rowbase + kk] = __float2bfloat16(0.0f);
    }
    // padding cols [1056,1088) for t = 1..511
    for (int e = threadIdx.x; e < 511 * 32; e += blockDim.x) {
        int t = (e >> 5) + 1;
        int k = SIGD + (e & 31);
        g_Ah[rowbase + (size_t)t * KPAD + k] = __float2bfloat16(0.0f);
        g_Al[rowbase + (size_t)t * KPAD + k] = __float2bfloat16(0.0f);
    }
    __syncthreads();

    const int i = threadIdx.x >> 5;
    const int j = threadIdx.x & 31;
    float S2 = 0.0f;
    float S1j = 0.0f;

    for (int t = 1; t < TT; ++t) {
        float dxj = s_x[t * DD + j] - s_x[(t - 1) * DD + j];
        float dxi = s_x[t * DD + i] - s_x[(t - 1) * DD + i];
        float S1i_prev = __shfl_sync(0xffffffffu, S1j, i);
        S2 += S1i_prev * dxj + 0.5f * dxi * dxj;
        S1j += dxj;
        float invt = 1.0f / (float)t;
        size_t row = rowbase + (size_t)t * KPAD;

        float v2 = S2 * invt;
        __nv_bfloat16 h2 = __float2bfloat16(v2);
        g_Ah[row + DD + i * DD + j] = h2;
        g_Al[row + DD + i * DD + j] = __float2bfloat16(v2 - __bfloat162float(h2));
        if (i == 0) {
            float v1 = S1j * invt;
            __nv_bfloat16 h1 = __float2bfloat16(v1);
            g_Ah[row + j] = h1;
            g_Al[row + j] = __float2bfloat16(v1 - __bfloat162float(h1));
        }
    }
}

// Kernel 1c: split B (forget kernel [1056][512]) into hi/lo bf16 [KPAD][512]
__global__ void split_B_kernel(const float* __restrict__ fk) {
    const size_t total = (size_t)KPAD * UU;
    for (size_t idx = blockIdx.x * 256 + threadIdx.x; idx < total;
         idx += (size_t)gridDim.x * 256) {
        int k = (int)(idx / UU);
        float v = (k < SIGD) ? fk[idx] : 0.0f;
        __nv_bfloat16 hi = __float2bfloat16(v);
        float lo = v - __bfloat162float(hi);
        g_Bh[idx] = hi;
        g_Bl[idx] = __float2bfloat16(lo);
    }
}

// ===========================================================================
// Kernel 2: WMMA bf16 3-split GEMM: g_fall = sigmoid(A@B + bias_f)
// ===========================================================================
__global__ __launch_bounds__(256) void fgemm_wmma_kernel(
    const float* __restrict__ bias, float* __restrict__ C) {
    __shared__ __nv_bfloat16 sAh[128][40];
    __shared__ __nv_bfloat16 sAl[128][40];
    __shared__ __nv_bfloat16 sBh[32][136];
    __shared__ __nv_bfloat16 sBl[32][136];
    __shared__ float sEpi[8][16][16];

    const int tid = threadIdx.x;
    const int warp = tid >> 5;
    const int lane = tid & 31;
    const int nt = blockIdx.x;
    const int mt = blockIdx.y;
    const int m0 = mt * 128;
    const int n0 = nt * 128;
    const int wm = warp & 3;
    const int wn = warp >> 2;

    wmma::fragment<wmma::accumulator, 16, 16, 16, float> acc[2][4];
#pragma unroll
    for (int im = 0; im < 2; ++im)
#pragma unroll
        for (int jn = 0; jn < 4; ++jn) wmma::fill_fragment(acc[im][jn], 0.0f);

    for (int k0 = 0; k0 < KPAD; k0 += 32) {
#pragma unroll
        for (int r = 0; r < 2; ++r) {
            int f = tid + r * 256;
            int row = f >> 2;
            int kc = (f & 3) * 8;
            size_t src = (size_t)(m0 + row) * KPAD + k0 + kc;
            *(uint4*)&sAh[row][kc] = *(const uint4*)&g_Ah[src];
            *(uint4*)&sAl[row][kc] = *(const uint4*)&g_Al[src];
        }
#pragma unroll
        for (int r = 0; r < 2; ++r) {
            int f = tid + r * 256;
            int kk = f >> 4;
            int nc = (f & 15) * 8;
            size_t src = (size_t)(k0 + kk) * UU + n0 + nc;
            *(uint4*)&sBh[kk][nc] = *(const uint4*)&g_Bh[src];
            *(uint4*)&sBl[kk][nc] = *(const uint4*)&g_Bl[src];
        }
        __syncthreads();

#pragma unroll
        for (int kk = 0; kk < 32; kk += 16) {
            wmma::fragment<wmma::matrix_b, 16, 16, 16, __nv_bfloat16,
                           wmma::row_major> bh[4], bl[4];
#pragma unroll
            for (int jn = 0; jn < 4; ++jn) {
                wmma::load_matrix_sync(bh[jn], &sBh[kk][wn * 64 + jn * 16], 136);
                wmma::load_matrix_sync(bl[jn], &sBl[kk][wn * 64 + jn * 16], 136);
            }
#pragma unroll
            for (int im = 0; im < 2; ++im) {
                wmma::fragment<wmma::matrix_a, 16, 16, 16, __nv_bfloat16,
                               wmma::row_major> ah, al;
                wmma::load_matrix_sync(ah, &sAh[wm * 32 + im * 16][kk], 40);
                wmma::load_matrix_sync(al, &sAl[wm * 32 + im * 16][kk], 40);
#pragma unroll
                for (int jn = 0; jn < 4; ++jn) {
                    wmma::mma_sync(acc[im][jn], ah, bh[jn], acc[im][jn]);
                    wmma::mma_sync(acc[im][jn], ah, bl[jn], acc[im][jn]);
                    wmma::mma_sync(acc[im][jn], al, bh[jn], acc[im][jn]);
                }
            }
        }
        __syncthreads();
    }

#pragma unroll
    for (int im = 0; im < 2; ++im) {
#pragma unroll
        for (int jn = 0; jn < 4; ++jn) {
            wmma::store_matrix_sync(&sEpi[warp][0][0], acc[im][jn], 16,
                                    wmma::mem_row_major);
            __syncwarp();
            int row = lane >> 1;
            int c0 = (lane & 1) * 8;
            int gm = m0 + wm * 32 + im * 16 + row;
            int gn = n0 + wn * 64 + jn * 16 + c0;
            float tmp[8];
#pragma unroll
            for (int q = 0; q < 8; ++q) {
                float v = sEpi[warp][row][c0 + q] + bias[512 + gn + q];
                tmp[q] = 1.0f / (1.0f + __expf(-v));
            }
            *(float4*)&C[(size_t)gm * UU + gn] =
                make_float4(tmp[0], tmp[1], tmp[2], tmp[3]);
            *(float4*)&C[(size_t)gm * UU + gn + 4] =
                make_float4(tmp[4], tmp[5], tmp[6], tmp[7]);
            __syncwarp();
        }
    }
}

// ===========================================================================
// Kernel 3: fp32 SGEMM for x projection (K=32) C = A@B + gate biases
// ===========================================================================
template <int KDIM, int NDIM>
__global__ __launch_bounds__(256) void sgemm_xproj_kernel(
    const float* __restrict__ A, const float* __restrict__ B,
    const float* __restrict__ bias, float* __restrict__ C) {
    __shared__ float As[16][132];
    __shared__ float Bs[16][132];
    const int tid = threadIdx.x;
    const int m0 = blockIdx.y * 128;
    const int n0 = blockIdx.x * 128;
    const int tx = tid & 15;
    const int ty = tid >> 4;

    float acc[8][8];
#pragma unroll
    for (int ii = 0; ii < 8; ++ii)
#pragma unroll
        for (int jj = 0; jj < 8; ++jj) acc[ii][jj] = 0.0f;

    for (int k0 = 0; k0 < KDIM; k0 += 16) {
#pragma unroll
        for (int r = 0; r < 2; ++r) {
            int f = tid + r * 256;
            int row = f >> 2;
            int kc = (f & 3) * 4;
            float4 v = *(const float4*)&A[(size_t)(m0 + row) * KDIM + k0 + kc];
            As[kc + 0][row] = v.x;
            As[kc + 1][row] = v.y;
            As[kc + 2][row] = v.z;
            As[kc + 3][row] = v.w;
        }
#pragma unroll
        for (int r = 0; r < 2; ++r) {
            int f = tid + r * 256;
            int kk = f >> 5;
            int nc = (f & 31) * 4;
            *(float4*)&Bs[kk][nc] =
                *(const float4*)&B[(size_t)(k0 + kk) * NDIM + n0 + nc];
        }
        __syncthreads();
#pragma unroll
        for (int kk = 0; kk < 16; ++kk) {
            float4 a0 = *(const float4*)&As[kk][ty * 8];
            float4 a1 = *(const float4*)&As[kk][ty * 8 + 4];
            float4 b0 = *(const float4*)&Bs[kk][tx * 8];
            float4 b1 = *(const float4*)&Bs[kk][tx * 8 + 4];
            float a[8] = {a0.x, a0.y, a0.z, a0.w, a1.x, a1.y, a1.z, a1.w};
            float bb[8] = {b0.x, b0.y, b0.z, b0.w, b1.x, b1.y, b1.z, b1.w};
#pragma unroll
            for (int ii = 0; ii < 8; ++ii)
#pragma unroll
                for (int jj = 0; jj < 8; ++jj) acc[ii][jj] += a[ii] * bb[jj];
        }
        __syncthreads();
    }

#pragma unroll
    for (int ii = 0; ii < 8; ++ii) {
        int m = m0 + ty * 8 + ii;
#pragma unroll
        for (int half = 0; half < 2; ++half) {
            float4 v;
            float tmp[4];
#pragma unroll
            for (int q = 0; q < 4; ++q) {
                int jj = half * 4 + q;
                int n = n0 + tx * 8 + jj;
                float val = acc[ii][jj];
                val += (n < 512) ? bias[n] : bias[n + 512];
                tmp[q] = val;
            }
            v.x = tmp[0]; v.y = tmp[1]; v.z = tmp[2]; v.w = tmp[3];
            *(float4*)&C[(size_t)m * NDIM + n0 + tx * 8 + half * 4] = v;
        }
    }
}

// ===========================================================================
// Kernel 4: persistent LSTM scan, WMMA bf16 hi/lo, weights in registers.
// 128 CTAs x 256 thr. CTA = (mi batch-group of 16, uj unit-slice of 16).
// Groups independent: per-group 32-CTA barrier. h in two ushort gmem planes.
// ===========================================================================
__global__ void reset_bar_kernel() {
    if (threadIdx.x < 4) g_bars[threadIdx.x][0] = 0u;
}

// smem layout (bytes)
#define SHH_B   0
#define SHL_B   16640                       // 16*520 ushorts
#define SOVL_B  33280                       // overlap: weight stage / sRed
#define SSTAGE_USH (512 * 56)               // 57344 B
#define SCAN_SMEM (SOVL_B + 57344)

__global__ __launch_bounds__(256, 1) void scan_kernel(
    const float* __restrict__ rk, float* __restrict__ out) {
    extern __shared__ char smraw[];
    unsigned short* sHh = (unsigned short*)(smraw + SHH_B);   // [16][520]
    unsigned short* sHl = (unsigned short*)(smraw + SHL_B);   // [16][520]
    unsigned short* sW  = (unsigned short*)(smraw + SOVL_B);  // [512][56] stage
    float* sRed = (float*)(smraw + SOVL_B);                   // [8][3][256]

    const int tid = threadIdx.x;
    const int warp = tid >> 5;
    const int mi = blockIdx.x >> 5;          // batch group 0..3
    const int uj = blockIdx.x & 31;          // unit slice 0..31
    const int B0 = mi * 16;
    const int U0 = uj * 16;
    volatile unsigned int* bar = &g_bars[mi][0];

    // ---- stage + load weight fragments (hi then lo), kept in registers ----
    wmma::fragment<wmma::matrix_b, 16, 16, 16, __nv_bfloat16,
                   wmma::row_major> bfr[2][4][3];
#pragma unroll
    for (int hl = 0; hl < 2; ++hl) {
        for (int idx = tid; idx < 512 * 48; idx += 256) {
            int k = idx / 48;
            int c = idx - k * 48;
            int gcol = (c >> 4) * 512 + U0 + (c & 15);
            float v = rk[(size_t)k * NG + gcol];
            __nv_bfloat16 hi = __float2bfloat16(v);
            if (hl == 0) {
                sW[k * 56 + c] = __bfloat16_as_ushort(hi);
            } else {
                float lo = v - __bfloat162float(hi);
                sW[k * 56 + c] = __bfloat16_as_ushort(__float2bfloat16(lo));
            }
        }
        __syncthreads();
#pragma unroll
        for (int kt = 0; kt < 4; ++kt)
#pragma unroll
            for (int n = 0; n < 3; ++n)
                wmma::load_matrix_sync(
                    bfr[hl][kt][n],
                    (__nv_bfloat16*)&sW[(warp * 64 + kt * 16) * 56 + n * 16], 56);
        __syncthreads();
    }

    const int bl_c = tid >> 4;               // owned cell batch local
    const int ul_c = tid & 15;               // owned cell unit local
    const int bglob = B0 + bl_c;
    const int uglob = U0 + ul_c;

    // zero h buffer 0 for owned cells
    g_hh[0][bglob][uglob] = 0;
    g_hl[0][bglob][uglob] = 0;
    __threadfence();
    __syncthreads();
    if (tid == 0) {
        atomicAdd((unsigned int*)bar, 1u);
        while (*bar < 32u) { }
        __threadfence();
    }
    __syncthreads();

    float c_state = 0.0f;
    int p = 0;

    // prefetch t = 0 time-parallel terms
    const float* xpb = g_xproj + (size_t)bglob * TT * NG + uglob;
    const float* fgb = g_fall + (size_t)bglob * TT * UU + uglob;
    float xpi = xpb[0], xpc = xpb[512], xpo = xpb[1024];
    float fgate = fgb[0];

    for (int t = 0; t < TT; ++t) {
        // ingest h block [16][512] (hi/lo planes) into smem — pure copy
        {
            const uint4* srcH = (const uint4*)&g_hh[p][B0][0];
            const uint4* srcL = (const uint4*)&g_hl[p][B0][0];
#pragma unroll
            for (int i = 0; i < 4; ++i) {
                int e = tid + i * 256;            // 0..1023
                int row = e >> 6;
                int c8 = (e & 63) * 8;
                *(uint4*)&sHh[row * 520 + c8] = __ldcg(&srcH[e]);
                *(uint4*)&sHl[row * 520 + c8] = __ldcg(&srcL[e]);
            }
        }
        __syncthreads();

        // warp `warp`: k in [warp*64, +64), 3 gate tiles, weights in regs
        {
            wmma::fragment<wmma::accumulator, 16, 16, 16, float> acc[3];
#pragma unroll
            for (int n = 0; n < 3; ++n) wmma::fill_fragment(acc[n], 0.0f);
#pragma unroll
            for (int kt = 0; kt < 4; ++kt) {
                int k0 = warp * 64 + kt * 16;
                wmma::fragment<wmma::matrix_a, 16, 16, 16, __nv_bfloat16,
                               wmma::row_major> ah, al;
                wmma::load_matrix_sync(ah, (__nv_bfloat16*)&sHh[k0], 520);
                wmma::load_matrix_sync(al, (__nv_bfloat16*)&sHl[k0], 520);
#pragma unroll
                for (int n = 0; n < 3; ++n) {
                    wmma::mma_sync(acc[n], ah, bfr[0][kt][n], acc[n]);
                    wmma::mma_sync(acc[n], ah, bfr[1][kt][n], acc[n]);
                    wmma::mma_sync(acc[n], al, bfr[0][kt][n], acc[n]);
                }
            }
#pragma unroll
            for (int n = 0; n < 3; ++n)
                wmma::store_matrix_sync(&sRed[(warp * 3 + n) * 256], acc[n], 16,
                                        wmma::mem_row_major);
        }
        __syncthreads();

        // cell update
        float gi = 0.0f, gc = 0.0f, go = 0.0f;
        const int cell = bl_c * 16 + ul_c;
#pragma unroll
        for (int w = 0; w < 8; ++w) {
            gi += sRed[(w * 3 + 0) * 256 + cell];
            gc += sRed[(w * 3 + 1) * 256 + cell];
            go += sRed[(w * 3 + 2) * 256 + cell];
        }
        float i_g = sigmoidf_(gi + xpi);
        float chat = tanhf_(gc + xpc);
        float o_g = sigmoidf_(go + xpo);
        c_state = fgate * c_state + i_g * chat;
        float h = o_g * tanhf_(c_state);

        if (t == TT - 1) {
            out[(size_t)bglob * UU + uglob] = h;
            break;
        }
        __nv_bfloat16 hb = __float2bfloat16(h);
        float lo = h - __bfloat162float(hb);
        g_hh[1 - p][bglob][uglob] = __bfloat16_as_ushort(hb);
        g_hl[1 - p][bglob][uglob] = __bfloat16_as_ushort(__float2bfloat16(lo));
        p ^= 1;

        __threadfence();
        __syncthreads();
        if (tid == 0) atomicAdd((unsigned int*)bar, 1u);
        // prefetch next step's time-parallel terms while waiting
        xpi = xpb[(size_t)(t + 1) * NG];
        xpc = xpb[(size_t)(t + 1) * NG + 512];
        xpo = xpb[(size_t)(t + 1) * NG + 1024];
        fgate = fgb[(size_t)(t + 1) * UU];
        if (tid == 0) {
            unsigned target = 32u * (unsigned)(t + 2);
            while (*bar < target) { }
            __threadfence();
        }
        __syncthreads();
    }
}

// ===========================================================================
// launcher
// ===========================================================================
extern "C" void kernel_launch(void* const* d_in, const int* in_sizes, int n_in,
                              void* d_out, int out_size) {
    const float* x    = (const float*)d_in[0];   // (64,512,32)
    const float* ik   = (const float*)d_in[1];   // (32,1536)
    const float* rk   = (const float*)d_in[2];   // (512,1536)
    const float* fk   = (const float*)d_in[3];   // (1056,512)
    const float* bias = (const float*)d_in[4];   // (2048,)
    float* out = (float*)d_out;

    cudaFuncSetAttribute(sig_kernel,
                         cudaFuncAttributeMaxDynamicSharedMemorySize, 64 * 1024);
    cudaFuncSetAttribute(scan_kernel,
                         cudaFuncAttributeMaxDynamicSharedMemorySize, SCAN_SMEM);

    float* xproj;  cudaGetSymbolAddress((void**)&xproj, g_xproj);
    float* fall;   cudaGetSymbolAddress((void**)&fall, g_fall);

    // 1. barrier reset
    reset_bar_kernel<<<1, 32>>>();

    // 2. signature stream -> bf16 hi/lo A operand directly
    sig_kernel<<<BATCH, 1024, TT * DD * sizeof(float)>>>(x);

    // 3. split B (forget kernel)
    split_B_kernel<<<256, 256>>>(fk);

    // 4. forget gate GEMM + sigmoid via WMMA bf16 3-split
    fgemm_wmma_kernel<<<dim3(UU / 128, MM / 128), 256>>>(bias, fall);

    // 5. input projection GEMM + gate biases (fp32 SGEMM, K=32)
    {
        dim3 grid(NG / 128, MM / 128);
        sgemm_xproj_kernel<DD, NG><<<grid, 256>>>(x, ik, bias, xproj);
    }

    // 6. persistent LSTM scan (profiled by ncu -s 5 -c 1)
    scan_kernel<<<NCTA, 256, SCAN_SMEM>>>(rk, out);
}

// round 6
// speedup vs baseline: 1.9588x; 1.1331x over previous
#include <cuda_runtime.h>
#include <cuda_bf16.h>
#include <mma.h>
#include <math.h>
#include <stdint.h>

using namespace nvcuda;

// Problem constants
#define BATCH 64
#define TT    512
#define DD    32
#define UU    512
#define SIGD  1056            // D + D*D
#define NG    1536            // 3*U
#define NCTA  128             // scan grid size
#define MM    (BATCH * TT)    // 32768
#define KPAD  1088            // 34 * 32

// ---------------- device scratch (static: no cudaMalloc allowed) ----------
__device__ float g_xproj[(size_t)MM * NG];                 // 201 MB  (bias fused)
__device__ float g_fall [(size_t)MM * UU];                 // 67 MB   (sigmoid fused)
__device__ unsigned short g_hh[2][BATCH][UU];              // h hi bf16 plane
__device__ unsigned short g_hl[2][BATCH][UU];              // h lo bf16 plane
__device__ unsigned int g_bars[4][32];                     // per-group barrier ctrs

// bf16 hi/lo split operands for the forget GEMM (row-major, K padded)
__device__ __nv_bfloat16 g_Ah[(size_t)MM * KPAD];          // 71 MB
__device__ __nv_bfloat16 g_Al[(size_t)MM * KPAD];          // 71 MB
__device__ __nv_bfloat16 g_Bh[(size_t)KPAD * UU];          // 1.1 MB
__device__ __nv_bfloat16 g_Bl[(size_t)KPAD * UU];

__device__ __forceinline__ float sigmoidf_(float v) {
    return 1.0f / (1.0f + __expf(-v));
}
__device__ __forceinline__ float tanhf_(float v) {
    return 2.0f / (1.0f + __expf(-2.0f * v)) - 1.0f;
}

__device__ __forceinline__ uint32_t smem_u32(const void* p) {
    uint32_t a;
    asm("{ .reg .u64 t; cvta.to.shared.u64 t, %1; cvt.u32.u64 %0, t; }"
        : "=r"(a) : "l"(p));
    return a;
}
__device__ __forceinline__ void cp16(uint32_t dst, const void* src) {
    asm volatile("cp.async.cg.shared.global [%0], [%1], 16;"
                 :: "r"(dst), "l"(src));
}

// ===========================================================================
// Kernel 1: signature stream -> g_Ah/g_Al directly (hi/lo bf16, [MM][KPAD])
// ===========================================================================
__global__ void sig_kernel(const float* __restrict__ x) {
    const int b = blockIdx.x;
    extern __shared__ float s_x[];           // 512*32 floats = 64KB
    for (int e = threadIdx.x; e < TT * DD; e += blockDim.x)
        s_x[e] = x[(size_t)b * TT * DD + e];

    const size_t rowbase = (size_t)b * TT * KPAD;
    for (int kk = threadIdx.x; kk < KPAD; kk += blockDim.x) {
        g_Ah[rowbase + kk] = __float2bfloat16(0.0f);
        g_Al[rowbase + kk] = __float2bfloat16(0.0f);
    }
    for (int e = threadIdx.x; e < 511 * 32; e += blockDim.x) {
        int t = (e >> 5) + 1;
        int k = SIGD + (e & 31);
        g_Ah[rowbase + (size_t)t * KPAD + k] = __float2bfloat16(0.0f);
        g_Al[rowbase + (size_t)t * KPAD + k] = __float2bfloat16(0.0f);
    }
    __syncthreads();

    const int i = threadIdx.x >> 5;
    const int j = threadIdx.x & 31;
    float S2 = 0.0f;
    float S1j = 0.0f;

    for (int t = 1; t < TT; ++t) {
        float dxj = s_x[t * DD + j] - s_x[(t - 1) * DD + j];
        float dxi = s_x[t * DD + i] - s_x[(t - 1) * DD + i];
        float S1i_prev = __shfl_sync(0xffffffffu, S1j, i);
        S2 += S1i_prev * dxj + 0.5f * dxi * dxj;
        S1j += dxj;
        float invt = 1.0f / (float)t;
        size_t row = rowbase + (size_t)t * KPAD;

        float v2 = S2 * invt;
        __nv_bfloat16 h2 = __float2bfloat16(v2);
        g_Ah[row + DD + i * DD + j] = h2;
        g_Al[row + DD + i * DD + j] = __float2bfloat16(v2 - __bfloat162float(h2));
        if (i == 0) {
            float v1 = S1j * invt;
            __nv_bfloat16 h1 = __float2bfloat16(v1);
            g_Ah[row + j] = h1;
            g_Al[row + j] = __float2bfloat16(v1 - __bfloat162float(h1));
        }
    }
}

// Kernel 1c: split B (forget kernel [1056][512]) into hi/lo bf16 [KPAD][512]
__global__ void split_B_kernel(const float* __restrict__ fk) {
    const size_t total = (size_t)KPAD * UU;
    for (size_t idx = blockIdx.x * 256 + threadIdx.x; idx < total;
         idx += (size_t)gridDim.x * 256) {
        int k = (int)(idx / UU);
        float v = (k < SIGD) ? fk[idx] : 0.0f;
        __nv_bfloat16 hi = __float2bfloat16(v);
        float lo = v - __bfloat162float(hi);
        g_Bh[idx] = hi;
        g_Bl[idx] = __float2bfloat16(lo);
    }
}

// ===========================================================================
// Kernel 2: WMMA bf16 3-split GEMM, cp.async double-buffered.
// g_fall = sigmoid(A@B + bias_f). CTA tile 128x128, BK=32, 34 k-iters.
// ===========================================================================
#define FG_A_BYTES (128 * 40 * 2)                 // 10240 per matrix
#define FG_B_BYTES (32 * 136 * 2)                 // 8704 per matrix
#define FG_STAGE   (2 * FG_A_BYTES + 2 * FG_B_BYTES)  // 37888
#define FG_EPI_OFF (2 * FG_STAGE)                 // 75776
#define FG_SMEM    (FG_EPI_OFF + 8 * 16 * 16 * 4) // 83968
#define FG_NIT     (KPAD / 32)                    // 34

__global__ __launch_bounds__(256) void fgemm_wmma_kernel(
    const float* __restrict__ bias, float* __restrict__ C) {
    extern __shared__ char smdyn[];
    const uint32_t sbase = smem_u32(smdyn);
    float* sEpi = (float*)(smdyn + FG_EPI_OFF);   // [8][256]

    const int tid = threadIdx.x;
    const int warp = tid >> 5;
    const int lane = tid & 31;
    const int nt = blockIdx.x;
    const int mt = blockIdx.y;
    const int m0 = mt * 128;
    const int n0 = nt * 128;
    const int wm = warp & 3;
    const int wn = warp >> 2;

    // per-thread copy coordinates (fixed across stages)
    const int a_row0 = tid >> 2,          a_kc0 = (tid & 3) * 8;
    const int a_row1 = (tid + 256) >> 2,  a_kc1 = ((tid + 256) & 3) * 8;
    const int b_kk0 = tid >> 4,           b_nc0 = (tid & 15) * 8;
    const int b_kk1 = (tid + 256) >> 4,   b_nc1 = ((tid + 256) & 15) * 8;

    auto issue = [&](int it, int s) {
        const int k0 = it * 32;
        const uint32_t st = sbase + s * FG_STAGE;
        const uint32_t stAh = st;
        const uint32_t stAl = st + FG_A_BYTES;
        const uint32_t stBh = st + 2 * FG_A_BYTES;
        const uint32_t stBl = st + 2 * FG_A_BYTES + FG_B_BYTES;
        cp16(stAh + (a_row0 * 40 + a_kc0) * 2,
             &g_Ah[(size_t)(m0 + a_row0) * KPAD + k0 + a_kc0]);
        cp16(stAh + (a_row1 * 40 + a_kc1) * 2,
             &g_Ah[(size_t)(m0 + a_row1) * KPAD + k0 + a_kc1]);
        cp16(stAl + (a_row0 * 40 + a_kc0) * 2,
             &g_Al[(size_t)(m0 + a_row0) * KPAD + k0 + a_kc0]);
        cp16(stAl + (a_row1 * 40 + a_kc1) * 2,
             &g_Al[(size_t)(m0 + a_row1) * KPAD + k0 + a_kc1]);
        cp16(stBh + (b_kk0 * 136 + b_nc0) * 2,
             &g_Bh[(size_t)(k0 + b_kk0) * UU + n0 + b_nc0]);
        cp16(stBh + (b_kk1 * 136 + b_nc1) * 2,
             &g_Bh[(size_t)(k0 + b_kk1) * UU + n0 + b_nc1]);
        cp16(stBl + (b_kk0 * 136 + b_nc0) * 2,
             &g_Bl[(size_t)(k0 + b_kk0) * UU + n0 + b_nc0]);
        cp16(stBl + (b_kk1 * 136 + b_nc1) * 2,
             &g_Bl[(size_t)(k0 + b_kk1) * UU + n0 + b_nc1]);
        asm volatile("cp.async.commit_group;");
    };

    wmma::fragment<wmma::accumulator, 16, 16, 16, float> acc[2][4];
#pragma unroll
    for (int im = 0; im < 2; ++im)
#pragma unroll
        for (int jn = 0; jn < 4; ++jn) wmma::fill_fragment(acc[im][jn], 0.0f);

    issue(0, 0);

    for (int it = 0; it < FG_NIT; ++it) {
        if (it + 1 < FG_NIT) {
            issue(it + 1, (it + 1) & 1);
            asm volatile("cp.async.wait_group 1;");
        } else {
            asm volatile("cp.async.wait_group 0;");
        }
        __syncthreads();

        const char* st = smdyn + (it & 1) * FG_STAGE;
        const __nv_bfloat16* pAh = (const __nv_bfloat16*)st;
        const __nv_bfloat16* pAl = (const __nv_bfloat16*)(st + FG_A_BYTES);
        const __nv_bfloat16* pBh = (const __nv_bfloat16*)(st + 2 * FG_A_BYTES);
        const __nv_bfloat16* pBl = (const __nv_bfloat16*)(st + 2 * FG_A_BYTES + FG_B_BYTES);

#pragma unroll
        for (int kk = 0; kk < 32; kk += 16) {
            wmma::fragment<wmma::matrix_b, 16, 16, 16, __nv_bfloat16,
                           wmma::row_major> bh[4], bl[4];
#pragma unroll
            for (int jn = 0; jn < 4; ++jn) {
                wmma::load_matrix_sync(bh[jn], pBh + kk * 136 + wn * 64 + jn * 16, 136);
                wmma::load_matrix_sync(bl[jn], pBl + kk * 136 + wn * 64 + jn * 16, 136);
            }
#pragma unroll
            for (int im = 0; im < 2; ++im) {
                wmma::fragment<wmma::matrix_a, 16, 16, 16, __nv_bfloat16,
                               wmma::row_major> ah, al;
                wmma::load_matrix_sync(ah, pAh + (wm * 32 + im * 16) * 40 + kk, 40);
                wmma::load_matrix_sync(al, pAl + (wm * 32 + im * 16) * 40 + kk, 40);
#pragma unroll
                for (int jn = 0; jn < 4; ++jn) {
                    wmma::mma_sync(acc[im][jn], ah, bh[jn], acc[im][jn]);
                    wmma::mma_sync(acc[im][jn], ah, bl[jn], acc[im][jn]);
                    wmma::mma_sync(acc[im][jn], al, bh[jn], acc[im][jn]);
                }
            }
        }
        __syncthreads();
    }

    // epilogue: sigmoid(acc + bias_f)
#pragma unroll
    for (int im = 0; im < 2; ++im) {
#pragma unroll
        for (int jn = 0; jn < 4; ++jn) {
            wmma::store_matrix_sync(&sEpi[warp * 256], acc[im][jn], 16,
                                    wmma::mem_row_major);
            __syncwarp();
            int row = lane >> 1;
            int c0 = (lane & 1) * 8;
            int gm = m0 + wm * 32 + im * 16 + row;
            int gn = n0 + wn * 64 + jn * 16 + c0;
            float tmp[8];
#pragma unroll
            for (int q = 0; q < 8; ++q) {
                float v = sEpi[warp * 256 + row * 16 + c0 + q] + bias[512 + gn + q];
                tmp[q] = 1.0f / (1.0f + __expf(-v));
            }
            *(float4*)&C[(size_t)gm * UU + gn] =
                make_float4(tmp[0], tmp[1], tmp[2], tmp[3]);
            *(float4*)&C[(size_t)gm * UU + gn + 4] =
                make_float4(tmp[4], tmp[5], tmp[6], tmp[7]);
            __syncwarp();
        }
    }
}

// ===========================================================================
// Kernel 3: fp32 SGEMM for x projection (K=32) C = A@B + gate biases
// ===========================================================================
template <int KDIM, int NDIM>
__global__ __launch_bounds__(256) void sgemm_xproj_kernel(
    const float* __restrict__ A, const float* __restrict__ B,
    const float* __restrict__ bias, float* __restrict__ C) {
    __shared__ float As[16][132];
    __shared__ float Bs[16][132];
    const int tid = threadIdx.x;
    const int m0 = blockIdx.y * 128;
    const int n0 = blockIdx.x * 128;
    const int tx = tid & 15;
    const int ty = tid >> 4;

    float acc[8][8];
#pragma unroll
    for (int ii = 0; ii < 8; ++ii)
#pragma unroll
        for (int jj = 0; jj < 8; ++jj) acc[ii][jj] = 0.0f;

    for (int k0 = 0; k0 < KDIM; k0 += 16) {
#pragma unroll
        for (int r = 0; r < 2; ++r) {
            int f = tid + r * 256;
            int row = f >> 2;
            int kc = (f & 3) * 4;
            float4 v = *(const float4*)&A[(size_t)(m0 + row) * KDIM + k0 + kc];
            As[kc + 0][row] = v.x;
            As[kc + 1][row] = v.y;
            As[kc + 2][row] = v.z;
            As[kc + 3][row] = v.w;
        }
#pragma unroll
        for (int r = 0; r < 2; ++r) {
            int f = tid + r * 256;
            int kk = f >> 5;
            int nc = (f & 31) * 4;
            *(float4*)&Bs[kk][nc] =
                *(const float4*)&B[(size_t)(k0 + kk) * NDIM + n0 + nc];
        }
        __syncthreads();
#pragma unroll
        for (int kk = 0; kk < 16; ++kk) {
            float4 a0 = *(const float4*)&As[kk][ty * 8];
            float4 a1 = *(const float4*)&As[kk][ty * 8 + 4];
            float4 b0 = *(const float4*)&Bs[kk][tx * 8];
            float4 b1 = *(const float4*)&Bs[kk][tx * 8 + 4];
            float a[8] = {a0.x, a0.y, a0.z, a0.w, a1.x, a1.y, a1.z, a1.w};
            float bb[8] = {b0.x, b0.y, b0.z, b0.w, b1.x, b1.y, b1.z, b1.w};
#pragma unroll
            for (int ii = 0; ii < 8; ++ii)
#pragma unroll
                for (int jj = 0; jj < 8; ++jj) acc[ii][jj] += a[ii] * bb[jj];
        }
        __syncthreads();
    }

#pragma unroll
    for (int ii = 0; ii < 8; ++ii) {
        int m = m0 + ty * 8 + ii;
#pragma unroll
        for (int half = 0; half < 2; ++half) {
            float4 v;
            float tmp[4];
#pragma unroll
            for (int q = 0; q < 4; ++q) {
                int jj = half * 4 + q;
                int n = n0 + tx * 8 + jj;
                float val = acc[ii][jj];
                val += (n < 512) ? bias[n] : bias[n + 512];
                tmp[q] = val;
            }
            v.x = tmp[0]; v.y = tmp[1]; v.z = tmp[2]; v.w = tmp[3];
            *(float4*)&C[(size_t)m * NDIM + n0 + tx * 8 + half * 4] = v;
        }
    }
}

// ===========================================================================
// Kernel 4: persistent LSTM scan, WMMA bf16 hi/lo, weights in registers.
// Barrier = bar.sync + release-atomic arrive + acquire-load poll (no membar).
// ===========================================================================
__global__ void reset_bar_kernel() {
    if (threadIdx.x < 4) g_bars[threadIdx.x][0] = 0u;
}

// smem layout (bytes)
#define SHH_B   0
#define SHL_B   16640                       // 16*520 ushorts
#define SOVL_B  33280                       // overlap: weight stage / sRed
#define SCAN_SMEM (SOVL_B + 57344)

__global__ __launch_bounds__(256, 1) void scan_kernel(
    const float* __restrict__ rk, float* __restrict__ out) {
    extern __shared__ char smraw[];
    unsigned short* sHh = (unsigned short*)(smraw + SHH_B);   // [16][520]
    unsigned short* sHl = (unsigned short*)(smraw + SHL_B);   // [16][520]
    unsigned short* sW  = (unsigned short*)(smraw + SOVL_B);  // [512][56] stage
    float* sRed = (float*)(smraw + SOVL_B);                   // [8][3][256]

    const int tid = threadIdx.x;
    const int warp = tid >> 5;
    const int mi = blockIdx.x >> 5;          // batch group 0..3
    const int uj = blockIdx.x & 31;          // unit slice 0..31
    const int B0 = mi * 16;
    const int U0 = uj * 16;
    unsigned int* bar = &g_bars[mi][0];

    // ---- stage + load weight fragments (hi then lo), kept in registers ----
    wmma::fragment<wmma::matrix_b, 16, 16, 16, __nv_bfloat16,
                   wmma::row_major> bfr[2][4][3];
#pragma unroll
    for (int hl = 0; hl < 2; ++hl) {
        for (int idx = tid; idx < 512 * 48; idx += 256) {
            int k = idx / 48;
            int c = idx - k * 48;
            int gcol = (c >> 4) * 512 + U0 + (c & 15);
            float v = rk[(size_t)k * NG + gcol];
            __nv_bfloat16 hi = __float2bfloat16(v);
            if (hl == 0) {
                sW[k * 56 + c] = __bfloat16_as_ushort(hi);
            } else {
                float lo = v - __bfloat162float(hi);
                sW[k * 56 + c] = __bfloat16_as_ushort(__float2bfloat16(lo));
            }
        }
        __syncthreads();
#pragma unroll
        for (int kt = 0; kt < 4; ++kt)
#pragma unroll
            for (int n = 0; n < 3; ++n)
                wmma::load_matrix_sync(
                    bfr[hl][kt][n],
                    (__nv_bfloat16*)&sW[(warp * 64 + kt * 16) * 56 + n * 16], 56);
        __syncthreads();
    }

    const int bl_c = tid >> 4;
    const int ul_c = tid & 15;
    const int bglob = B0 + bl_c;
    const int uglob = U0 + ul_c;

    // zero h buffer 0 for owned cells, then group barrier (release/acquire)
    g_hh[0][bglob][uglob] = 0;
    g_hl[0][bglob][uglob] = 0;
    __syncthreads();
    if (tid == 0) {
        unsigned old;
        asm volatile("atom.global.add.release.gpu.u32 %0, [%1], 1;"
                     : "=r"(old) : "l"(bar) : "memory");
        unsigned v = 0;
        do {
            asm volatile("ld.global.acquire.gpu.u32 %0, [%1];"
                         : "=r"(v) : "l"(bar) : "memory");
        } while (v < 32u);
    }
    __syncthreads();

    float c_state = 0.0f;
    int p = 0;

    const float* xpb = g_xproj + (size_t)bglob * TT * NG + uglob;
    const float* fgb = g_fall + (size_t)bglob * TT * UU + uglob;
    float xpi = xpb[0], xpc = xpb[512], xpo = xpb[1024];
    float fgate = fgb[0];

    for (int t = 0; t < TT; ++t) {
        // ingest h block [16][512] (hi/lo planes) into smem
        {
            const uint4* srcH = (const uint4*)&g_hh[p][B0][0];
            const uint4* srcL = (const uint4*)&g_hl[p][B0][0];
#pragma unroll
            for (int i = 0; i < 4; ++i) {
                int e = tid + i * 256;
                int row = e >> 6;
                int c8 = (e & 63) * 8;
                *(uint4*)&sHh[row * 520 + c8] = __ldcg(&srcH[e]);
                *(uint4*)&sHl[row * 520 + c8] = __ldcg(&srcL[e]);
            }
        }
        __syncthreads();

        // warp-level HMMA over k range, weights in registers
        {
            wmma::fragment<wmma::accumulator, 16, 16, 16, float> acc[3];
#pragma unroll
            for (int n = 0; n < 3; ++n) wmma::fill_fragment(acc[n], 0.0f);
#pragma unroll
            for (int kt = 0; kt < 4; ++kt) {
                int k0 = warp * 64 + kt * 16;
                wmma::fragment<wmma::matrix_a, 16, 16, 16, __nv_bfloat16,
                               wmma::row_major> ah, al;
                wmma::load_matrix_sync(ah, (__nv_bfloat16*)&sHh[k0], 520);
                wmma::load_matrix_sync(al, (__nv_bfloat16*)&sHl[k0], 520);
#pragma unroll
                for (int n = 0; n < 3; ++n) {
                    wmma::mma_sync(acc[n], ah, bfr[0][kt][n], acc[n]);
                    wmma::mma_sync(acc[n], ah, bfr[1][kt][n], acc[n]);
                    wmma::mma_sync(acc[n], al, bfr[0][kt][n], acc[n]);
                }
            }
#pragma unroll
            for (int n = 0; n < 3; ++n)
                wmma::store_matrix_sync(&sRed[(warp * 3 + n) * 256], acc[n], 16,
                                        wmma::mem_row_major);
        }
        __syncthreads();

        // cell update
        float gi = 0.0f, gc = 0.0f, go = 0.0f;
        const int cell = bl_c * 16 + ul_c;
#pragma unroll
        for (int w = 0; w < 8; ++w) {
            gi += sRed[(w * 3 + 0) * 256 + cell];
            gc += sRed[(w * 3 + 1) * 256 + cell];
            go += sRed[(w * 3 + 2) * 256 + cell];
        }
        float i_g = sigmoidf_(gi + xpi);
        float chat = tanhf_(gc + xpc);
        float o_g = sigmoidf_(go + xpo);
        c_state = fgate * c_state + i_g * chat;
        float h = o_g * tanhf_(c_state);

        if (t == TT - 1) {
            out[(size_t)bglob * UU + uglob] = h;
            break;
        }
        __nv_bfloat16 hb = __float2bfloat16(h);
        float lo = h - __bfloat162float(hb);
        g_hh[1 - p][bglob][uglob] = __bfloat16_as_ushort(hb);
        g_hl[1 - p][bglob][uglob] = __bfloat16_as_ushort(__float2bfloat16(lo));
        p ^= 1;

        __syncthreads();
        if (tid == 0) {
            unsigned old;
            asm volatile("atom.global.add.release.gpu.u32 %0, [%1], 1;"
                         : "=r"(old) : "l"(bar) : "memory");
        }
        // prefetch next step's time-parallel terms while waiting
        xpi = xpb[(size_t)(t + 1) * NG];
        xpc = xpb[(size_t)(t + 1) * NG + 512];
        xpo = xpb[(size_t)(t + 1) * NG + 1024];
        fgate = fgb[(size_t)(t + 1) * UU];
        if (tid == 0) {
            unsigned target = 32u * (unsigned)(t + 2);
            unsigned v = 0;
            do {
                asm volatile("ld.global.acquire.gpu.u32 %0, [%1];"
                             : "=r"(v) : "l"(bar) : "memory");
            } while (v < target);
        }
        __syncthreads();
    }
}

// ===========================================================================
// launcher
// ===========================================================================
extern "C" void kernel_launch(void* const* d_in, const int* in_sizes, int n_in,
                              void* d_out, int out_size) {
    const float* x    = (const float*)d_in[0];   // (64,512,32)
    const float* ik   = (const float*)d_in[1];   // (32,1536)
    const float* rk   = (const float*)d_in[2];   // (512,1536)
    const float* fk   = (const float*)d_in[3];   // (1056,512)
    const float* bias = (const float*)d_in[4];   // (2048,)
    float* out = (float*)d_out;

    cudaFuncSetAttribute(sig_kernel,
                         cudaFuncAttributeMaxDynamicSharedMemorySize, 64 * 1024);
    cudaFuncSetAttribute(fgemm_wmma_kernel,
                         cudaFuncAttributeMaxDynamicSharedMemorySize, FG_SMEM);
    cudaFuncSetAttribute(scan_kernel,
                         cudaFuncAttributeMaxDynamicSharedMemorySize, SCAN_SMEM);

    float* xproj;  cudaGetSymbolAddress((void**)&xproj, g_xproj);
    float* fall;   cudaGetSymbolAddress((void**)&fall, g_fall);

    // 1. barrier reset
    reset_bar_kernel<<<1, 32>>>();

    // 2. signature stream -> bf16 hi/lo A operand directly
    sig_kernel<<<BATCH, 1024, TT * DD * sizeof(float)>>>(x);

    // 3. split B (forget kernel)
    split_B_kernel<<<256, 256>>>(fk);

    // 4. forget gate GEMM + sigmoid (WMMA bf16 3-split, cp.async dbuf)
    fgemm_wmma_kernel<<<dim3(UU / 128, MM / 128), 256, FG_SMEM>>>(bias, fall);

    // 5. input projection GEMM + gate biases (fp32 SGEMM, K=32)
    {
        dim3 grid(NG / 128, MM / 128);
        sgemm_xproj_kernel<DD, NG><<<grid, 256>>>(x, ik, bias, xproj);
    }

    // 6. persistent LSTM scan (profiled by ncu -s 5 -c 1)
    scan_kernel<<<NCTA, 256, SCAN_SMEM>>>(rk, out);
}

// round 7
// speedup vs baseline: 2.2922x; 1.1702x over previous
#include <cuda_runtime.h>
#include <cuda_bf16.h>
#include <mma.h>
#include <math.h>
#include <stdint.h>

using namespace nvcuda;

// Problem constants
#define BATCH 64
#define TT    512
#define DD    32
#define UU    512
#define SIGD  1056            // D + D*D
#define NG    1536            // 3*U
#define NCTA  128             // scan grid size
#define MM    (BATCH * TT)    // 32768
#define KPAD  1088            // 34 * 32

// ---------------- device scratch (static: no cudaMalloc allowed) ----------
__device__ float g_xproj[(size_t)MM * NG];                 // 201 MB  (bias fused)
__device__ float g_fall [(size_t)MM * UU];                 // 67 MB   (sigmoid fused)
__device__ unsigned short g_hh[2][BATCH][UU];              // h hi bf16 plane
__device__ unsigned short g_hl[2][BATCH][UU];              // h lo bf16 plane
__device__ unsigned int g_bars[4][32];                     // per-group barrier ctrs

// bf16 hi/lo split operands for the forget GEMM (row-major, K padded)
__device__ __nv_bfloat16 g_Ah[(size_t)MM * KPAD];          // 71 MB
__device__ __nv_bfloat16 g_Al[(size_t)MM * KPAD];          // 71 MB
__device__ __nv_bfloat16 g_Bh[(size_t)KPAD * UU];          // 1.1 MB
__device__ __nv_bfloat16 g_Bl[(size_t)KPAD * UU];

__device__ __forceinline__ float sigmoidf_(float v) {
    return 1.0f / (1.0f + __expf(-v));
}
__device__ __forceinline__ float tanhf_(float v) {
    return 2.0f / (1.0f + __expf(-2.0f * v)) - 1.0f;
}

__device__ __forceinline__ uint32_t smem_u32(const void* p) {
    uint32_t a;
    asm("{ .reg .u64 t; cvta.to.shared.u64 t, %1; cvt.u32.u64 %0, t; }"
        : "=r"(a) : "l"(p));
    return a;
}
__device__ __forceinline__ void cp16(uint32_t dst, const void* src) {
    asm volatile("cp.async.cg.shared.global [%0], [%1], 16;"
                 :: "r"(dst), "l"(src));
}

// ===========================================================================
// Kernel 1: signature stream -> g_Ah/g_Al directly (hi/lo bf16, [MM][KPAD])
// ===========================================================================
__global__ void sig_kernel(const float* __restrict__ x) {
    const int b = blockIdx.x;
    extern __shared__ float s_x[];           // 512*32 floats = 64KB
    for (int e = threadIdx.x; e < TT * DD; e += blockDim.x)
        s_x[e] = x[(size_t)b * TT * DD + e];

    const size_t rowbase = (size_t)b * TT * KPAD;
    for (int kk = threadIdx.x; kk < KPAD; kk += blockDim.x) {
        g_Ah[rowbase + kk] = __float2bfloat16(0.0f);
        g_Al[rowbase + kk] = __float2bfloat16(0.0f);
    }
    for (int e = threadIdx.x; e < 511 * 32; e += blockDim.x) {
        int t = (e >> 5) + 1;
        int k = SIGD + (e & 31);
        g_Ah[rowbase + (size_t)t * KPAD + k] = __float2bfloat16(0.0f);
        g_Al[rowbase + (size_t)t * KPAD + k] = __float2bfloat16(0.0f);
    }
    __syncthreads();

    const int i = threadIdx.x >> 5;
    const int j = threadIdx.x & 31;
    float S2 = 0.0f;
    float S1j = 0.0f;

    for (int t = 1; t < TT; ++t) {
        float dxj = s_x[t * DD + j] - s_x[(t - 1) * DD + j];
        float dxi = s_x[t * DD + i] - s_x[(t - 1) * DD + i];
        float S1i_prev = __shfl_sync(0xffffffffu, S1j, i);
        S2 += S1i_prev * dxj + 0.5f * dxi * dxj;
        S1j += dxj;
        float invt = 1.0f / (float)t;
        size_t row = rowbase + (size_t)t * KPAD;

        float v2 = S2 * invt;
        __nv_bfloat16 h2 = __float2bfloat16(v2);
        g_Ah[row + DD + i * DD + j] = h2;
        g_Al[row + DD + i * DD + j] = __float2bfloat16(v2 - __bfloat162float(h2));
        if (i == 0) {
            float v1 = S1j * invt;
            __nv_bfloat16 h1 = __float2bfloat16(v1);
            g_Ah[row + j] = h1;
            g_Al[row + j] = __float2bfloat16(v1 - __bfloat162float(h1));
        }
    }
}

// Kernel 1c: split B (forget kernel [1056][512]) into hi/lo bf16 [KPAD][512]
__global__ void split_B_kernel(const float* __restrict__ fk) {
    const size_t total = (size_t)KPAD * UU;
    for (size_t idx = blockIdx.x * 256 + threadIdx.x; idx < total;
         idx += (size_t)gridDim.x * 256) {
        int k = (int)(idx / UU);
        float v = (k < SIGD) ? fk[idx] : 0.0f;
        __nv_bfloat16 hi = __float2bfloat16(v);
        float lo = v - __bfloat162float(hi);
        g_Bh[idx] = hi;
        g_Bl[idx] = __float2bfloat16(lo);
    }
}

// ===========================================================================
// Kernel 2: WMMA bf16 3-split GEMM, cp.async double-buffered, 2 CTAs/SM.
// ===========================================================================
#define FG_A_BYTES (128 * 40 * 2)
#define FG_B_BYTES (32 * 136 * 2)
#define FG_STAGE   (2 * FG_A_BYTES + 2 * FG_B_BYTES)
#define FG_EPI_OFF (2 * FG_STAGE)
#define FG_SMEM    (FG_EPI_OFF + 8 * 16 * 16 * 4)
#define FG_NIT     (KPAD / 32)

__global__ __launch_bounds__(256, 2) void fgemm_wmma_kernel(
    const float* __restrict__ bias, float* __restrict__ C) {
    extern __shared__ char smdyn[];
    const uint32_t sbase = smem_u32(smdyn);
    float* sEpi = (float*)(smdyn + FG_EPI_OFF);

    const int tid = threadIdx.x;
    const int warp = tid >> 5;
    const int lane = tid & 31;
    const int nt = blockIdx.x;
    const int mt = blockIdx.y;
    const int m0 = mt * 128;
    const int n0 = nt * 128;
    const int wm = warp & 3;
    const int wn = warp >> 2;

    const int a_row0 = tid >> 2,          a_kc0 = (tid & 3) * 8;
    const int a_row1 = (tid + 256) >> 2,  a_kc1 = ((tid + 256) & 3) * 8;
    const int b_kk0 = tid >> 4,           b_nc0 = (tid & 15) * 8;
    const int b_kk1 = (tid + 256) >> 4,   b_nc1 = ((tid + 256) & 15) * 8;

    auto issue = [&](int it, int s) {
        const int k0 = it * 32;
        const uint32_t st = sbase + s * FG_STAGE;
        const uint32_t stAh = st;
        const uint32_t stAl = st + FG_A_BYTES;
        const uint32_t stBh = st + 2 * FG_A_BYTES;
        const uint32_t stBl = st + 2 * FG_A_BYTES + FG_B_BYTES;
        cp16(stAh + (a_row0 * 40 + a_kc0) * 2,
             &g_Ah[(size_t)(m0 + a_row0) * KPAD + k0 + a_kc0]);
        cp16(stAh + (a_row1 * 40 + a_kc1) * 2,
             &g_Ah[(size_t)(m0 + a_row1) * KPAD + k0 + a_kc1]);
        cp16(stAl + (a_row0 * 40 + a_kc0) * 2,
             &g_Al[(size_t)(m0 + a_row0) * KPAD + k0 + a_kc0]);
        cp16(stAl + (a_row1 * 40 + a_kc1) * 2,
             &g_Al[(size_t)(m0 + a_row1) * KPAD + k0 + a_kc1]);
        cp16(stBh + (b_kk0 * 136 + b_nc0) * 2,
             &g_Bh[(size_t)(k0 + b_kk0) * UU + n0 + b_nc0]);
        cp16(stBh + (b_kk1 * 136 + b_nc1) * 2,
             &g_Bh[(size_t)(k0 + b_kk1) * UU + n0 + b_nc1]);
        cp16(stBl + (b_kk0 * 136 + b_nc0) * 2,
             &g_Bl[(size_t)(k0 + b_kk0) * UU + n0 + b_nc0]);
        cp16(stBl + (b_kk1 * 136 + b_nc1) * 2,
             &g_Bl[(size_t)(k0 + b_kk1) * UU + n0 + b_nc1]);
        asm volatile("cp.async.commit_group;");
    };

    wmma::fragment<wmma::accumulator, 16, 16, 16, float> acc[2][4];
#pragma unroll
    for (int im = 0; im < 2; ++im)
#pragma unroll
        for (int jn = 0; jn < 4; ++jn) wmma::fill_fragment(acc[im][jn], 0.0f);

    issue(0, 0);

    for (int it = 0; it < FG_NIT; ++it) {
        if (it + 1 < FG_NIT) {
            issue(it + 1, (it + 1) & 1);
            asm volatile("cp.async.wait_group 1;");
        } else {
            asm volatile("cp.async.wait_group 0;");
        }
        __syncthreads();

        const char* st = smdyn + (it & 1) * FG_STAGE;
        const __nv_bfloat16* pAh = (const __nv_bfloat16*)st;
        const __nv_bfloat16* pAl = (const __nv_bfloat16*)(st + FG_A_BYTES);
        const __nv_bfloat16* pBh = (const __nv_bfloat16*)(st + 2 * FG_A_BYTES);
        const __nv_bfloat16* pBl = (const __nv_bfloat16*)(st + 2 * FG_A_BYTES + FG_B_BYTES);

#pragma unroll
        for (int kk = 0; kk < 32; kk += 16) {
            wmma::fragment<wmma::matrix_b, 16, 16, 16, __nv_bfloat16,
                           wmma::row_major> bh[4], bl[4];
#pragma unroll
            for (int jn = 0; jn < 4; ++jn) {
                wmma::load_matrix_sync(bh[jn], pBh + kk * 136 + wn * 64 + jn * 16, 136);
                wmma::load_matrix_sync(bl[jn], pBl + kk * 136 + wn * 64 + jn * 16, 136);
            }
#pragma unroll
            for (int im = 0; im < 2; ++im) {
                wmma::fragment<wmma::matrix_a, 16, 16, 16, __nv_bfloat16,
                               wmma::row_major> ah, al;
                wmma::load_matrix_sync(ah, pAh + (wm * 32 + im * 16) * 40 + kk, 40);
                wmma::load_matrix_sync(al, pAl + (wm * 32 + im * 16) * 40 + kk, 40);
#pragma unroll
                for (int jn = 0; jn < 4; ++jn) {
                    wmma::mma_sync(acc[im][jn], ah, bh[jn], acc[im][jn]);
                    wmma::mma_sync(acc[im][jn], ah, bl[jn], acc[im][jn]);
                    wmma::mma_sync(acc[im][jn], al, bh[jn], acc[im][jn]);
                }
            }
        }
        __syncthreads();
    }

#pragma unroll
    for (int im = 0; im < 2; ++im) {
#pragma unroll
        for (int jn = 0; jn < 4; ++jn) {
            wmma::store_matrix_sync(&sEpi[warp * 256], acc[im][jn], 16,
                                    wmma::mem_row_major);
            __syncwarp();
            int row = lane >> 1;
            int c0 = (lane & 1) * 8;
            int gm = m0 + wm * 32 + im * 16 + row;
            int gn = n0 + wn * 64 + jn * 16 + c0;
            float tmp[8];
#pragma unroll
            for (int q = 0; q < 8; ++q) {
                float v = sEpi[warp * 256 + row * 16 + c0 + q] + bias[512 + gn + q];
                tmp[q] = 1.0f / (1.0f + __expf(-v));
            }
            *(float4*)&C[(size_t)gm * UU + gn] =
                make_float4(tmp[0], tmp[1], tmp[2], tmp[3]);
            *(float4*)&C[(size_t)gm * UU + gn + 4] =
                make_float4(tmp[4], tmp[5], tmp[6], tmp[7]);
            __syncwarp();
        }
    }
}

// ===========================================================================
// Kernel 3: fp32 SGEMM for x projection (K=32) C = A@B + gate biases
// ===========================================================================
template <int KDIM, int NDIM>
__global__ __launch_bounds__(256) void sgemm_xproj_kernel(
    const float* __restrict__ A, const float* __restrict__ B,
    const float* __restrict__ bias, float* __restrict__ C) {
    __shared__ float As[16][132];
    __shared__ float Bs[16][132];
    const int tid = threadIdx.x;
    const int m0 = blockIdx.y * 128;
    const int n0 = blockIdx.x * 128;
    const int tx = tid & 15;
    const int ty = tid >> 4;

    float acc[8][8];
#pragma unroll
    for (int ii = 0; ii < 8; ++ii)
#pragma unroll
        for (int jj = 0; jj < 8; ++jj) acc[ii][jj] = 0.0f;

    for (int k0 = 0; k0 < KDIM; k0 += 16) {
#pragma unroll
        for (int r = 0; r < 2; ++r) {
            int f = tid + r * 256;
            int row = f >> 2;
            int kc = (f & 3) * 4;
            float4 v = *(const float4*)&A[(size_t)(m0 + row) * KDIM + k0 + kc];
            As[kc + 0][row] = v.x;
            As[kc + 1][row] = v.y;
            As[kc + 2][row] = v.z;
            As[kc + 3][row] = v.w;
        }
#pragma unroll
        for (int r = 0; r < 2; ++r) {
            int f = tid + r * 256;
            int kk = f >> 5;
            int nc = (f & 31) * 4;
            *(float4*)&Bs[kk][nc] =
                *(const float4*)&B[(size_t)(k0 + kk) * NDIM + n0 + nc];
        }
        __syncthreads();
#pragma unroll
        for (int kk = 0; kk < 16; ++kk) {
            float4 a0 = *(const float4*)&As[kk][ty * 8];
            float4 a1 = *(const float4*)&As[kk][ty * 8 + 4];
            float4 b0 = *(const float4*)&Bs[kk][tx * 8];
            float4 b1 = *(const float4*)&Bs[kk][tx * 8 + 4];
            float a[8] = {a0.x, a0.y, a0.z, a0.w, a1.x, a1.y, a1.z, a1.w};
            float bb[8] = {b0.x, b0.y, b0.z, b0.w, b1.x, b1.y, b1.z, b1.w};
#pragma unroll
            for (int ii = 0; ii < 8; ++ii)
#pragma unroll
                for (int jj = 0; jj < 8; ++jj) acc[ii][jj] += a[ii] * bb[jj];
        }
        __syncthreads();
    }

#pragma unroll
    for (int ii = 0; ii < 8; ++ii) {
        int m = m0 + ty * 8 + ii;
#pragma unroll
        for (int half = 0; half < 2; ++half) {
            float4 v;
            float tmp[4];
#pragma unroll
            for (int q = 0; q < 4; ++q) {
                int jj = half * 4 + q;
                int n = n0 + tx * 8 + jj;
                float val = acc[ii][jj];
                val += (n < 512) ? bias[n] : bias[n + 512];
                tmp[q] = val;
            }
            v.x = tmp[0]; v.y = tmp[1]; v.z = tmp[2]; v.w = tmp[3];
            *(float4*)&C[(size_t)m * NDIM + n0 + tx * 8 + half * 4] = v;
        }
    }
}

// ===========================================================================
// Kernel 4: persistent LSTM scan — warp-autonomous step front half.
// All threads acquire-poll; each warp ingests only its own k-slice of h,
// then goes straight to MMA behind __syncwarp. Only 2 block syncs per step.
// ===========================================================================
__global__ void reset_bar_kernel() {
    if (threadIdx.x < 4) g_bars[threadIdx.x][0] = 0u;
}

#define SHH_B   0
#define SHL_B   16640
#define SOVL_B  33280
#define SCAN_SMEM (SOVL_B + 57344)

__global__ __launch_bounds__(256, 1) void scan_kernel(
    const float* __restrict__ rk, float* __restrict__ out) {
    extern __shared__ char smraw[];
    unsigned short* sHh = (unsigned short*)(smraw + SHH_B);   // [16][520]
    unsigned short* sHl = (unsigned short*)(smraw + SHL_B);   // [16][520]
    unsigned short* sW  = (unsigned short*)(smraw + SOVL_B);  // [512][56] stage
    float* sRed = (float*)(smraw + SOVL_B);                   // [8][3][256]

    const int tid = threadIdx.x;
    const int warp = tid >> 5;
    const int lane = tid & 31;
    const int mi = blockIdx.x >> 5;          // batch group 0..3
    const int uj = blockIdx.x & 31;          // unit slice 0..31
    const int B0 = mi * 16;
    const int U0 = uj * 16;
    unsigned int* bar = &g_bars[mi][0];

    // ---- stage + load weight fragments (hi then lo), kept in registers ----
    wmma::fragment<wmma::matrix_b, 16, 16, 16, __nv_bfloat16,
                   wmma::row_major> bfr[2][4][3];
#pragma unroll
    for (int hl = 0; hl < 2; ++hl) {
        for (int idx = tid; idx < 512 * 48; idx += 256) {
            int k = idx / 48;
            int c = idx - k * 48;
            int gcol = (c >> 4) * 512 + U0 + (c & 15);
            float v = rk[(size_t)k * NG + gcol];
            __nv_bfloat16 hi = __float2bfloat16(v);
            if (hl == 0) {
                sW[k * 56 + c] = __bfloat16_as_ushort(hi);
            } else {
                float lo = v - __bfloat162float(hi);
                sW[k * 56 + c] = __bfloat16_as_ushort(__float2bfloat16(lo));
            }
        }
        __syncthreads();
#pragma unroll
        for (int kt = 0; kt < 4; ++kt)
#pragma unroll
            for (int n = 0; n < 3; ++n)
                wmma::load_matrix_sync(
                    bfr[hl][kt][n],
                    (__nv_bfloat16*)&sW[(warp * 64 + kt * 16) * 56 + n * 16], 56);
        __syncthreads();
    }

    const int bl_c = tid >> 4;
    const int ul_c = tid & 15;
    const int bglob = B0 + bl_c;
    const int uglob = U0 + ul_c;

    // zero h buffer 0 for owned cells, then release-arrive
    g_hh[0][bglob][uglob] = 0;
    g_hl[0][bglob][uglob] = 0;
    __syncthreads();
    if (tid == 0) {
        unsigned old;
        asm volatile("atom.global.add.release.gpu.u32 %0, [%1], 1;"
                     : "=r"(old) : "l"(bar) : "memory");
    }

    float c_state = 0.0f;
    int p = 0;
    unsigned target = 32u;

    const float* xpb = g_xproj + (size_t)bglob * TT * NG + uglob;
    const float* fgb = g_fall + (size_t)bglob * TT * UU + uglob;
    float xpi = xpb[0], xpc = xpb[512], xpo = xpb[1024];
    float fgate = fgb[0];

    for (int t = 0; t < TT; ++t) {
        // all threads acquire-poll the group flag (same line -> broadcast)
        {
            unsigned v;
            do {
                asm volatile("ld.global.acquire.gpu.u32 %0, [%1];"
                             : "=r"(v) : "l"(bar) : "memory");
            } while (v < target);
        }

        // warp-private ingest: this warp's 64-col k-slice of h, both planes
        {
            const unsigned short* srcH = &g_hh[p][B0][0];
            const unsigned short* srcL = &g_hl[p][B0][0];
#pragma unroll
            for (int i = 0; i < 4; ++i) {
                int c = lane + 32 * i;          // 0..127
                int row = c >> 3;               // 0..15
                int col = warp * 64 + (c & 7) * 8;
                *(uint4*)&sHh[row * 520 + col] =
                    __ldcg((const uint4*)&srcH[row * UU + col]);
                *(uint4*)&sHl[row * 520 + col] =
                    __ldcg((const uint4*)&srcL[row * UU + col]);
            }
        }
        __syncwarp();

        // warp MMA over its own k-slice; weights in registers
        {
            wmma::fragment<wmma::accumulator, 16, 16, 16, float> acc[3];
#pragma unroll
            for (int n = 0; n < 3; ++n) wmma::fill_fragment(acc[n], 0.0f);
#pragma unroll
            for (int kt = 0; kt < 4; ++kt) {
                int k0 = warp * 64 + kt * 16;
                wmma::fragment<wmma::matrix_a, 16, 16, 16, __nv_bfloat16,
                               wmma::row_major> ah, al;
                wmma::load_matrix_sync(ah, (__nv_bfloat16*)&sHh[k0], 520);
                wmma::load_matrix_sync(al, (__nv_bfloat16*)&sHl[k0], 520);
#pragma unroll
                for (int n = 0; n < 3; ++n) {
                    wmma::mma_sync(acc[n], ah, bfr[0][kt][n], acc[n]);
                    wmma::mma_sync(acc[n], ah, bfr[1][kt][n], acc[n]);
                    wmma::mma_sync(acc[n], al, bfr[0][kt][n], acc[n]);
                }
            }
#pragma unroll
            for (int n = 0; n < 3; ++n)
                wmma::store_matrix_sync(&sRed[(warp * 3 + n) * 256], acc[n], 16,
                                        wmma::mem_row_major);
        }
        __syncthreads();                         // sRed complete

        // cell update
        float gi = 0.0f, gc = 0.0f, go = 0.0f;
        const int cell = bl_c * 16 + ul_c;
#pragma unroll
        for (int w = 0; w < 8; ++w) {
            gi += sRed[(w * 3 + 0) * 256 + cell];
            gc += sRed[(w * 3 + 1) * 256 + cell];
            go += sRed[(w * 3 + 2) * 256 + cell];
        }
        float i_g = sigmoidf_(gi + xpi);
        float chat = tanhf_(gc + xpc);
        float o_g = sigmoidf_(go + xpo);
        c_state = fgate * c_state + i_g * chat;
        float h = o_g * tanhf_(c_state);

        if (t == TT - 1) {
            out[(size_t)bglob * UU + uglob] = h;
            break;
        }
        __nv_bfloat16 hb = __float2bfloat16(h);
        float lo = h - __bfloat162float(hb);
        g_hh[1 - p][bglob][uglob] = __bfloat16_as_ushort(hb);
        g_hl[1 - p][bglob][uglob] = __bfloat16_as_ushort(__float2bfloat16(lo));
        p ^= 1;

        __syncthreads();                         // all h stores issued
        if (tid == 0) {
            unsigned old;
            asm volatile("atom.global.add.release.gpu.u32 %0, [%1], 1;"
                         : "=r"(old) : "l"(bar) : "memory");
        }
        target += 32u;
        // prefetch next step's time-parallel terms
        xpi = xpb[(size_t)(t + 1) * NG];
        xpc = xpb[(size_t)(t + 1) * NG + 512];
        xpo = xpb[(size_t)(t + 1) * NG + 1024];
        fgate = fgb[(size_t)(t + 1) * UU];
    }
}

// ===========================================================================
// launcher
// ===========================================================================
extern "C" void kernel_launch(void* const* d_in, const int* in_sizes, int n_in,
                              void* d_out, int out_size) {
    const float* x    = (const float*)d_in[0];   // (64,512,32)
    const float* ik   = (const float*)d_in[1];   // (32,1536)
    const float* rk   = (const float*)d_in[2];   // (512,1536)
    const float* fk   = (const float*)d_in[3];   // (1056,512)
    const float* bias = (const float*)d_in[4];   // (2048,)
    float* out = (float*)d_out;

    cudaFuncSetAttribute(sig_kernel,
                         cudaFuncAttributeMaxDynamicSharedMemorySize, 64 * 1024);
    cudaFuncSetAttribute(fgemm_wmma_kernel,
                         cudaFuncAttributeMaxDynamicSharedMemorySize, FG_SMEM);
    cudaFuncSetAttribute(scan_kernel,
                         cudaFuncAttributeMaxDynamicSharedMemorySize, SCAN_SMEM);

    float* xproj;  cudaGetSymbolAddress((void**)&xproj, g_xproj);
    float* fall;   cudaGetSymbolAddress((void**)&fall, g_fall);

    // 1. barrier reset
    reset_bar_kernel<<<1, 32>>>();

    // 2. signature stream -> bf16 hi/lo A operand directly
    sig_kernel<<<BATCH, 1024, TT * DD * sizeof(float)>>>(x);

    // 3. split B (forget kernel)
    split_B_kernel<<<256, 256>>>(fk);

    // 4. forget gate GEMM + sigmoid (WMMA bf16 3-split, cp.async, 2 CTA/SM)
    fgemm_wmma_kernel<<<dim3(UU / 128, MM / 128), 256, FG_SMEM>>>(bias, fall);

    // 5. input projection GEMM + gate biases (fp32 SGEMM, K=32)
    {
        dim3 grid(NG / 128, MM / 128);
        sgemm_xproj_kernel<DD, NG><<<grid, 256>>>(x, ik, bias, xproj);
    }

    // 6. persistent LSTM scan
    scan_kernel<<<NCTA, 256, SCAN_SMEM>>>(rk, out);
}